// round 2
// baseline (speedup 1.0000x reference)
#include <cuda_runtime.h>
#include <math.h>

// ---------------- problem constants ----------------
#define B        128
#define TV       256
#define TS       40
#define VIN      1024
#define VHID     512
#define SIN      300
#define SHID     256
#define NCAT     2624
#define NFEAT    1024
#define LCROSS   512
#define NLOC     64

#define VF_ELEMS   ((size_t)B*TV*2*VHID)        // 33554432
#define SF_ELEMS   ((size_t)B*2*SHID)           // 65536
#define FT_ELEMS   ((size_t)B*NFEAT)            // 131072

// ---------------- scratch (__device__ globals; no allocation allowed) --------
__device__ float g_xp_v[(size_t)B*TV*3072];     // [b*TV+t][d*1536+g]   402 MB
__device__ float g_xp_s[(size_t)B*TS*1536];     // [b*TS+t][d*768+g]
__device__ float g_h_v[2*2*B*VHID];             // [buf][d][b][j]
__device__ float g_h_s[2*2*B*SHID];
__device__ float g_words[(size_t)B*TS*2*SHID];  // sentence GRU outputs
__device__ float g_lmean[B*1024];
__device__ float g_rmean[B*1024];
__device__ float g_cat[B*NCAT];
__device__ float g_sproj[B*LCROSS];

// ---------------- init ----------------
__global__ void zero_h_kernel(float* hv, float* hs) {
    int i = blockIdx.x * blockDim.x + threadIdx.x;
    if (i < 2*2*B*VHID) hv[i] = 0.f;
    if (i < 2*2*B*SHID) hs[i] = 0.f;
}

// ---------------- big GEMM: C[M,N] = A[M,K] @ W[N,K]^T + bias ----------------
// 128x128 tile, BK=8, 256 threads, 8x8 microtile. Optional row-validity skip:
// rows are (b = row/T, t = row%T); a tile is skipped when every row has t>=lens[b]
// (its consumers are masked, and masked consumers use selects so stale data is safe).
__global__ __launch_bounds__(256) void gemm_bias(
    const float* __restrict__ A, const float* __restrict__ W,
    const float* __restrict__ bias, float* __restrict__ C,
    int M, int N, int K, const int* __restrict__ lens, int T)
{
    const int n0 = blockIdx.x * 128;
    const int m0 = blockIdx.y * 128;
    __shared__ __align__(16) float As[8][132];
    __shared__ __align__(16) float Bs[8][132];
    __shared__ int s_any;
    const int tid = threadIdx.x;

    if (lens) {
        if (tid == 0) {
            int any = 0;
            for (int r = 0; r < 128; r++) {
                int row = m0 + r;
                if (row % T < lens[row / T]) { any = 1; break; }
            }
            s_any = any;
        }
        __syncthreads();
        if (!s_any) return;
        __syncthreads();
    }

    const int ty = tid / 16, tx = tid % 16;
    float acc[8][8];
#pragma unroll
    for (int i = 0; i < 8; i++)
#pragma unroll
        for (int j = 0; j < 8; j++) acc[i][j] = 0.f;

    for (int k0 = 0; k0 < K; k0 += 8) {
        for (int e = tid; e < 1024; e += 256) {
            int row = e / 8, kk = e % 8;
            int kg = k0 + kk;
            As[kk][row] = (kg < K) ? A[(size_t)(m0 + row) * K + kg] : 0.f;
            Bs[kk][row] = (kg < K) ? W[(size_t)(n0 + row) * K + kg] : 0.f;
        }
        __syncthreads();
#pragma unroll
        for (int kk = 0; kk < 8; kk++) {
            float ar[8], br[8];
            *(float4*)&ar[0] = *(const float4*)&As[kk][ty * 8];
            *(float4*)&ar[4] = *(const float4*)&As[kk][ty * 8 + 4];
            *(float4*)&br[0] = *(const float4*)&Bs[kk][tx * 8];
            *(float4*)&br[4] = *(const float4*)&Bs[kk][tx * 8 + 4];
#pragma unroll
            for (int i = 0; i < 8; i++)
#pragma unroll
                for (int j = 0; j < 8; j++) acc[i][j] += ar[i] * br[j];
        }
        __syncthreads();
    }

#pragma unroll
    for (int i = 0; i < 8; i++) {
        int m = m0 + ty * 8 + i;
#pragma unroll
        for (int j = 0; j < 8; j++) {
            int n = n0 + tx * 8 + j;
            C[(size_t)m * N + n] = acc[i][j] + bias[n];
        }
    }
}

// ---------------- fused GRU step ----------------
// One launch per timestep; grid (dir=2, B/32, H/32). Computes hp = hin @ w_hh^T
// for the CTA's 32 batch rows x {r,z,n} x 32 hidden cols, then gates + masked
// update. hin/hout double buffered (no cross-CTA RAW hazard within a step).
__global__ __launch_bounds__(256) void gru_step(
    const float* __restrict__ xp, const float* __restrict__ w_hh,
    const float* __restrict__ b_hh,
    const float* __restrict__ hin, float* __restrict__ hout,
    float* __restrict__ out, const int* __restrict__ len,
    int t, int H, int T)
{
    const int d  = blockIdx.x;
    const int b0 = blockIdx.y * 32;
    const int j0 = blockIdx.z * 32;
    const int t_eff = (d == 0) ? t : (T - 1 - t);
    const int tid = threadIdx.x;
    const int outLd = 2 * H;

    __shared__ __align__(16) float hs[32][34];   // [k][b]
    __shared__ __align__(16) float ws[32][98];   // [k][c]  c: gate*32 + jlocal
    __shared__ float hp[32][96];                 // [b][c]
    __shared__ int s_any;

    if (tid == 0) {
        int any = 0;
        for (int r = 0; r < 32; r++) if (t_eff < len[b0 + r]) { any = 1; break; }
        s_any = any;
    }
    __syncthreads();

    const float* hbase = hin  + (size_t)d * B * H;
    float*       obase = hout + (size_t)d * B * H;

    if (!s_any) {  // all rows masked: h passes through, outputs are zero
        for (int e = tid; e < 1024; e += 256) {
            int j = e % 32, b = e / 32;
            int bg = b0 + b, jg = j0 + j;
            obase[(size_t)bg * H + jg] = hbase[(size_t)bg * H + jg];
            out[((size_t)bg * T + t_eff) * outLd + d * H + jg] = 0.f;
        }
        return;
    }

    const float* wbase = w_hh + (size_t)d * 3 * H * H;
    const int ty = tid / 16, tx = tid % 16;
    float acc[2][6];
#pragma unroll
    for (int i = 0; i < 2; i++)
#pragma unroll
        for (int j = 0; j < 6; j++) acc[i][j] = 0.f;

    for (int k0 = 0; k0 < H; k0 += 32) {
        for (int e = tid; e < 1024; e += 256) {
            int b = e / 32, k = e % 32;
            hs[k][b] = hbase[(size_t)(b0 + b) * H + k0 + k];
        }
        for (int e = tid; e < 3072; e += 256) {
            int c = e / 32, k = e % 32;
            int g = (c / 32) * H + j0 + (c % 32);
            ws[k][c] = wbase[(size_t)g * H + k0 + k];
        }
        __syncthreads();
#pragma unroll
        for (int k = 0; k < 32; k++) {
            float2 hv = *(const float2*)&hs[k][ty * 2];
            float2 w0 = *(const float2*)&ws[k][tx * 6];
            float2 w1 = *(const float2*)&ws[k][tx * 6 + 2];
            float2 w2 = *(const float2*)&ws[k][tx * 6 + 4];
            acc[0][0] += hv.x * w0.x;  acc[0][1] += hv.x * w0.y;
            acc[0][2] += hv.x * w1.x;  acc[0][3] += hv.x * w1.y;
            acc[0][4] += hv.x * w2.x;  acc[0][5] += hv.x * w2.y;
            acc[1][0] += hv.y * w0.x;  acc[1][1] += hv.y * w0.y;
            acc[1][2] += hv.y * w1.x;  acc[1][3] += hv.y * w1.y;
            acc[1][4] += hv.y * w2.x;  acc[1][5] += hv.y * w2.y;
        }
        __syncthreads();
    }

#pragma unroll
    for (int i = 0; i < 2; i++)
#pragma unroll
        for (int j = 0; j < 6; j++) hp[ty * 2 + i][tx * 6 + j] = acc[i][j];
    __syncthreads();

    const float* bb = b_hh + (size_t)d * 3 * H;
    for (int e = tid; e < 1024; e += 256) {
        int j = e % 32, b = e / 32;
        int bg = b0 + b, jg = j0 + j;
        int m = (t_eff < len[bg]);
        float hold = hbase[(size_t)bg * H + jg];
        const float* xr = xp + ((size_t)bg * T + t_eff) * (6 * H) + (size_t)d * 3 * H;
        float xrv = xr[jg], xzv = xr[H + jg], xnv = xr[2 * H + jg];
        float hpr = hp[b][j]      + bb[jg];
        float hpz = hp[b][32 + j] + bb[H + jg];
        float hpn = hp[b][64 + j] + bb[2 * H + jg];
        float r = 1.f / (1.f + expf(-(xrv + hpr)));
        float z = 1.f / (1.f + expf(-(xzv + hpz)));
        float n = tanhf(xnv + r * hpn);
        float hnew = (1.f - z) * n + z * hold;
        obase[(size_t)bg * H + jg] = m ? hnew : hold;             // select: NaN-safe
        out[((size_t)bg * T + t_eff) * outLd + d * H + jg] = m ? hnew : 0.f;
    }
}

// ---------------- segment means over visual_fea ----------------
__global__ __launch_bounds__(256) void seg_mean_kernel(
    const float* __restrict__ vf, const float* __restrict__ loc,
    const int* __restrict__ v_len,
    float* __restrict__ lmean, float* __restrict__ rmean, float* __restrict__ cat)
{
    const int b = blockIdx.x;
    const int col = blockIdx.y * 256 + threadIdx.x;   // grid.y = 4 -> 1024 cols
    const int vl = v_len[b];
    const float scale = (float)(vl - 1);
    const float l0 = loc[b * 2], l1 = loc[b * 2 + 1];
    const int cond = (l0 <= l1);
    const float lhi = cond ? l0 : 0.f;
    const float rlo = cond ? l1 : 1.f;
    const int lend   = (int)floorf(lhi * scale);
    const int rstart = (int)floorf(rlo * scale);
    const int rend   = vl - 1;
    const int ok_l = (0 <= lend);
    const int ok_r = (rstart <= rend);

    float ls = 0.f, rs = 0.f, gs = 0.f;
    for (int t = 0; t < TV; t++) {
        float v = vf[((size_t)b * TV + t) * 1024 + col];
        if (t < vl) gs += v;
        if (ok_l && t <= lend) ls += v;
        if (ok_r && t >= rstart && t <= rend) rs += v;
    }
    float lcnt = ok_l ? (float)(lend + 1) : 1.f;
    float rcnt = ok_r ? (float)(rend - rstart + 1) : 1.f;
    if (lcnt < 1.f) lcnt = 1.f;
    if (rcnt < 1.f) rcnt = 1.f;
    lmean[b * 1024 + col] = ls / lcnt;
    rmean[b * 1024 + col] = rs / rcnt;
    cat[(size_t)b * NCAT + 512 + col] = gs / (float)vl;
}

// ---------------- gather sen_fea = words[b, lens[b]-1, :] ----------------
__global__ void gather_senfea(const float* __restrict__ words,
                              const int* __restrict__ lens,
                              float* __restrict__ out_sf, float* __restrict__ cat)
{
    const int b = blockIdx.x;
    const int t = lens[b] - 1;
    for (int c = threadIdx.x; c < 2 * SHID; c += blockDim.x) {
        float v = words[((size_t)b * TS + t) * (2 * SHID) + c];
        out_sf[(size_t)b * (2 * SHID) + c] = v;
        cat[(size_t)b * NCAT + c] = v;
    }
}

// ---------------- small GEMM with epilogue (bias, optional mul, optional relu)
__global__ __launch_bounds__(256) void gemm_small(
    const float* __restrict__ A, const float* __restrict__ W,
    const float* __restrict__ bias, const float* __restrict__ mul, int mulLd,
    float* __restrict__ C, int ldC, int M, int N, int K, int relu)
{
    const int n0 = blockIdx.x * 32, m0 = blockIdx.y * 32;
    __shared__ __align__(16) float As[32][34];
    __shared__ __align__(16) float Ws[32][34];
    const int tid = threadIdx.x, ty = tid / 16, tx = tid % 16;
    float acc[2][2] = {{0.f, 0.f}, {0.f, 0.f}};

    for (int k0 = 0; k0 < K; k0 += 32) {
        for (int e = tid; e < 1024; e += 256) {
            int r = e / 32, k = e % 32;
            int kg = k0 + k;
            As[k][r] = (kg < K) ? A[(size_t)(m0 + r) * K + kg] : 0.f;
            Ws[k][r] = (kg < K) ? W[(size_t)(n0 + r) * K + kg] : 0.f;
        }
        __syncthreads();
#pragma unroll
        for (int k = 0; k < 32; k++) {
            float2 av = *(const float2*)&As[k][ty * 2];
            float2 wv = *(const float2*)&Ws[k][tx * 2];
            acc[0][0] += av.x * wv.x;  acc[0][1] += av.x * wv.y;
            acc[1][0] += av.y * wv.x;  acc[1][1] += av.y * wv.y;
        }
        __syncthreads();
    }
#pragma unroll
    for (int i = 0; i < 2; i++) {
        int m = m0 + ty * 2 + i;
#pragma unroll
        for (int j = 0; j < 2; j++) {
            int n = n0 + tx * 2 + j;
            float v = acc[i][j] + bias[n];
            if (mul) v *= mul[(size_t)m * mulLd + n];
            if (relu) v = fmaxf(v, 0.f);
            C[(size_t)m * ldC + n] = v;
        }
    }
}

// ---------------- launch ----------------
extern "C" void kernel_launch(void* const* d_in, const int* in_sizes, int n_in,
                              void* d_out, int out_size)
{
    const float* gv     = (const float*)d_in[1];
    const float* sen    = (const float*)d_in[2];
    const float* loc    = (const float*)d_in[5];
    const int*   lens   = (const int*)  d_in[6];
    const int*   v_len  = (const int*)  d_in[7];
    const float* v_w_ih = (const float*)d_in[8];
    const float* v_w_hh = (const float*)d_in[9];
    const float* v_b_ih = (const float*)d_in[10];
    const float* v_b_hh = (const float*)d_in[11];
    const float* s_w_ih = (const float*)d_in[12];
    const float* s_w_hh = (const float*)d_in[13];
    const float* s_b_ih = (const float*)d_in[14];
    const float* s_b_hh = (const float*)d_in[15];
    const float* fc1_w  = (const float*)d_in[16];
    const float* fc1_b  = (const float*)d_in[17];
    const float* fc2_w  = (const float*)d_in[18];
    const float* fc2_b  = (const float*)d_in[19];
    const float* fc3_w  = (const float*)d_in[20];
    const float* fc3_b  = (const float*)d_in[21];
    const float* fc4_w  = (const float*)d_in[22];
    const float* fc4_b  = (const float*)d_in[23];

    float* out    = (float*)d_out;
    float* out_vf = out;                          // [B,TV,1024]
    float* out_sf = out + VF_ELEMS;               // [B,512]
    float* out_ft = out + VF_ELEMS + SF_ELEMS;    // [B,1024]

    float *xp_v, *xp_s, *h_v, *h_s, *words, *lmean, *rmean, *cat, *sproj;
    cudaGetSymbolAddress((void**)&xp_v,  g_xp_v);
    cudaGetSymbolAddress((void**)&xp_s,  g_xp_s);
    cudaGetSymbolAddress((void**)&h_v,   g_h_v);
    cudaGetSymbolAddress((void**)&h_s,   g_h_s);
    cudaGetSymbolAddress((void**)&words, g_words);
    cudaGetSymbolAddress((void**)&lmean, g_lmean);
    cudaGetSymbolAddress((void**)&rmean, g_rmean);
    cudaGetSymbolAddress((void**)&cat,   g_cat);
    cudaGetSymbolAddress((void**)&sproj, g_sproj);

    // 1. zero hidden state (both GRUs)
    zero_h_kernel<<<(2*2*B*VHID + 255) / 256, 256>>>(h_v, h_s);

    // 2. input projections (masked-row tile skip)
    gemm_bias<<<dim3(3072/128, (B*TV)/128), 256>>>(gv,  v_w_ih, v_b_ih, xp_v,
                                                   B*TV, 3072, VIN, v_len, TV);
    gemm_bias<<<dim3(1536/128, (B*TS)/128), 256>>>(sen, s_w_ih, s_b_ih, xp_s,
                                                   B*TS, 1536, SIN, lens, TS);

    // 3. visual GRU recurrence (256 steps, double-buffered h)
    const int HVBUF = 2 * B * VHID;
    for (int t = 0; t < TV; t++) {
        gru_step<<<dim3(2, B/32, VHID/32), 256>>>(
            xp_v, v_w_hh, v_b_hh,
            h_v + (size_t)(t & 1) * HVBUF, h_v + (size_t)((t + 1) & 1) * HVBUF,
            out_vf, v_len, t, VHID, TV);
    }

    // 4. sentence GRU recurrence (40 steps)
    const int HSBUF = 2 * B * SHID;
    for (int t = 0; t < TS; t++) {
        gru_step<<<dim3(2, B/32, SHID/32), 256>>>(
            xp_s, s_w_hh, s_b_hh,
            h_s + (size_t)(t & 1) * HSBUF, h_s + (size_t)((t + 1) & 1) * HSBUF,
            words, lens, t, SHID, TS);
    }

    // 5. sen_fea gather (into d_out and into cat cols [0,512))
    gather_senfea<<<B, 256>>>(words, lens, out_sf, cat);

    // 6. segment means + global mean (gv_fea straight into cat cols [512,1536))
    seg_mean_kernel<<<dim3(B, 4), 256>>>(out_vf, loc, v_len, lmean, rmean, cat);

    // 7. FC stack
    gemm_small<<<dim3(LCROSS/32, B/32), 256>>>(out_sf, fc2_w, fc2_b, nullptr, 0,
                                               sproj, LCROSS, B, LCROSS, 2*SHID, 0);
    gemm_small<<<dim3(LCROSS/32, B/32), 256>>>(lmean, fc1_w, fc1_b, sproj, LCROSS,
                                               cat + 1536, NCAT, B, LCROSS, 2*VHID, 1);
    gemm_small<<<dim3(LCROSS/32, B/32), 256>>>(rmean, fc1_w, fc1_b, sproj, LCROSS,
                                               cat + 2048, NCAT, B, LCROSS, 2*VHID, 1);
    gemm_small<<<dim3(NLOC/32, B/32), 256>>>(loc, fc3_w, fc3_b, nullptr, 0,
                                             cat + 2560, NCAT, B, NLOC, 2, 1);
    gemm_small<<<dim3(NFEAT/32, B/32), 256>>>(cat, fc4_w, fc4_b, nullptr, 0,
                                              out_ft, NFEAT, B, NFEAT, NCAT, 1);
}

// round 3
// speedup vs baseline: 1.6708x; 1.6708x over previous
#include <cuda_runtime.h>
#include <math.h>

// ---------------- problem constants ----------------
#define B        128
#define TV       256
#define TS       40
#define VIN      1024
#define VHID     512
#define SIN      300
#define SHID     256
#define NCAT     2624
#define NFEAT    1024
#define LCROSS   512
#define NLOC     64

#define VF_ELEMS   ((size_t)B*TV*2*VHID)
#define SF_ELEMS   ((size_t)B*2*SHID)

// ---------------- scratch (__device__ globals) ----------------
__device__ float g_xp_v[(size_t)B*TV*3072];     // [b*TV+t][d*1536+g*512+j]
__device__ float g_xp_s[(size_t)B*TS*1536];     // [b*TS+t][d*768+g*256+j]
__device__ float g_h_v[2*2*B*VHID];             // [buf][d][r][j]  (r = permuted)
__device__ float g_h_s[2*2*B*SHID];
__device__ float g_part_v[8*2*B*1536];          // [ks][d][r][1536]
__device__ float g_part_s[4*2*B*768];
__device__ float g_words[(size_t)B*TS*2*SHID];
__device__ float g_lmean[B*1024];
__device__ float g_rmean[B*1024];
__device__ float g_cat[B*NCAT];
__device__ float g_sproj[B*LCROSS];
__device__ int   g_perm_v[B], g_lenp_v[B];
__device__ int   g_perm_s[B], g_lenp_s[B];
__device__ unsigned g_bar[4];                   // [cnt_v, gen_v, cnt_s, gen_s]

// ---------------- init: sort batches by length (desc) + zero barriers ------
__global__ void sort_init_kernel(const int* __restrict__ v_len,
                                 const int* __restrict__ lens,
                                 int* pv, int* lv, int* ps, int* ls,
                                 unsigned* bar)
{
    int i = threadIdx.x;                // 128 threads
    if (i < 4) bar[i] = 0u;
    int a = v_len[i], rank = 0;
    for (int j = 0; j < B; j++) {
        int c = v_len[j];
        rank += (c > a) || (c == a && j < i);
    }
    pv[rank] = i; lv[rank] = a;
    a = lens[i]; rank = 0;
    for (int j = 0; j < B; j++) {
        int c = lens[j];
        rank += (c > a) || (c == a && j < i);
    }
    ps[rank] = i; ls[rank] = a;
}

__global__ void zero_h_kernel(float* hv, float* hs) {
    int i = blockIdx.x * blockDim.x + threadIdx.x;
    if (i < 2*2*B*VHID) hv[i] = 0.f;
    if (i < 2*2*B*SHID) hs[i] = 0.f;
}

// ---------------- big GEMM: C[M,N] = A[M,K] @ W[N,K]^T + bias --------------
__global__ __launch_bounds__(256) void gemm_bias(
    const float* __restrict__ A, const float* __restrict__ W,
    const float* __restrict__ bias, float* __restrict__ C,
    int M, int N, int K, const int* __restrict__ lens, int T)
{
    const int n0 = blockIdx.x * 128;
    const int m0 = blockIdx.y * 128;
    __shared__ __align__(16) float As[8][132];
    __shared__ __align__(16) float Bs[8][132];
    __shared__ int s_any;
    const int tid = threadIdx.x;

    if (lens) {
        if (tid == 0) {
            int any = 0;
            for (int r = 0; r < 128; r++) {
                int row = m0 + r;
                if (row % T < lens[row / T]) { any = 1; break; }
            }
            s_any = any;
        }
        __syncthreads();
        if (!s_any) return;
        __syncthreads();
    }

    const int ty = tid / 16, tx = tid % 16;
    float acc[8][8];
#pragma unroll
    for (int i = 0; i < 8; i++)
#pragma unroll
        for (int j = 0; j < 8; j++) acc[i][j] = 0.f;

    for (int k0 = 0; k0 < K; k0 += 8) {
        for (int e = tid; e < 1024; e += 256) {
            int row = e / 8, kk = e % 8;
            int kg = k0 + kk;
            As[kk][row] = (kg < K) ? A[(size_t)(m0 + row) * K + kg] : 0.f;
            Bs[kk][row] = (kg < K) ? W[(size_t)(n0 + row) * K + kg] : 0.f;
        }
        __syncthreads();
#pragma unroll
        for (int kk = 0; kk < 8; kk++) {
            float ar[8], br[8];
            *(float4*)&ar[0] = *(const float4*)&As[kk][ty * 8];
            *(float4*)&ar[4] = *(const float4*)&As[kk][ty * 8 + 4];
            *(float4*)&br[0] = *(const float4*)&Bs[kk][tx * 8];
            *(float4*)&br[4] = *(const float4*)&Bs[kk][tx * 8 + 4];
#pragma unroll
            for (int i = 0; i < 8; i++)
#pragma unroll
                for (int j = 0; j < 8; j++) acc[i][j] += ar[i] * br[j];
        }
        __syncthreads();
    }

#pragma unroll
    for (int i = 0; i < 8; i++) {
        int m = m0 + ty * 8 + i;
#pragma unroll
        for (int j = 0; j < 8; j++) {
            int n = n0 + tx * 8 + j;
            C[(size_t)m * N + n] = acc[i][j] + bias[n];
        }
    }
}

// ---------------- software grid barrier ----------------
__device__ __forceinline__ void grid_sync(unsigned* bar, int ncta, unsigned* gen)
{
    __syncthreads();
    if (threadIdx.x == 0) {
        unsigned target = *gen + 1u;
        __threadfence();
        unsigned arr = atomicAdd(&bar[0], 1u);
        if (arr == (unsigned)(ncta - 1)) {
            atomicExch(&bar[0], 0u);
            __threadfence();
            atomicExch(&bar[1], target);
        } else {
            while (atomicAdd(&bar[1], 0u) < target) __nanosleep(64);
        }
        __threadfence();
        *gen = target;
    }
    __syncthreads();
}

// ---------------- persistent weight-stationary bidirectional GRU ----------
// Grid: 2(dir) * NCT(col-tiles of 96 over 3H) * KS(K-slices of 64). 256 thr.
// Phase1: partial hp = h @ W_hh^T per (col-tile, K-slice). Phase2: reduce over
// K-slices + bias + gates + masked update. Batch rows permuted desc-by-len so
// per-thread mask skips are coherent. h double-buffered in global.
template<int H, int G3, int T, int NCT, int KS>
__global__ __launch_bounds__(256) void gru_persistent(
    const float* __restrict__ xp, const float* __restrict__ w_hh,
    const float* __restrict__ b_hh, float* __restrict__ hbuf,
    float* __restrict__ part, float* __restrict__ out,
    const int* __restrict__ perm, const int* __restrict__ lenp,
    unsigned* __restrict__ bar)
{
    constexpr int KC = 64;                 // K per slice; KS*KC == H
    constexpr int NCTA = 2 * NCT * KS;
    extern __shared__ float sm[];
    float* Ws = sm;                        // [KC][98]
    float* Hs = sm + KC * 98;              // [KC][132]

    const int cta = blockIdx.x;
    const int d   = cta / (NCT * KS);
    const int ct  = (cta % (NCT * KS)) / KS;
    const int ks  = cta % KS;
    const int c0  = ct * 96;
    const int k0  = ks * KC;
    const int tid = threadIdx.x;
    const int ty  = tid / 16, tx = tid % 16;
    const int r0  = ty * 8, cc = tx * 6;

    // load stationary W tile: Ws[k][c] = w_hh[d][c0+c][k0+k]
    for (int e = tid; e < KC * 96; e += 256) {
        int k = e % KC, c = e / KC;
        Ws[k * 98 + c] = w_hh[((size_t)d * G3 + c0 + c) * H + k0 + k];
    }

    const int myLen = lenp[r0];            // max len among this thread's 8 rows
    unsigned gen = 0;
    float* hcur = hbuf;
    float* hnxt = hbuf + 2 * B * H;
    const int total = 2 * B * H;
    const int nth   = NCTA * 256;

    for (int t = 0; t < T; t++) {
        const int te1 = (d == 0) ? t : (T - 1 - t);

        // stage h slice: Hs[k][r] = hcur[d][r][k0+k]
        for (int e = tid; e < KC * B; e += 256) {
            int k = e % KC, r = e / KC;
            Hs[k * 132 + r] = hcur[((size_t)d * B + r) * H + k0 + k];
        }
        __syncthreads();

        if (te1 < myLen) {
            float acc[8][6];
#pragma unroll
            for (int i = 0; i < 8; i++)
#pragma unroll
                for (int j = 0; j < 6; j++) acc[i][j] = 0.f;
#pragma unroll 4
            for (int k = 0; k < KC; k++) {
                float hv[8], wv[6];
                *(float4*)&hv[0] = *(const float4*)&Hs[k * 132 + r0];
                *(float4*)&hv[4] = *(const float4*)&Hs[k * 132 + r0 + 4];
                *(float2*)&wv[0] = *(const float2*)&Ws[k * 98 + cc];
                *(float2*)&wv[2] = *(const float2*)&Ws[k * 98 + cc + 2];
                *(float2*)&wv[4] = *(const float2*)&Ws[k * 98 + cc + 4];
#pragma unroll
                for (int i = 0; i < 8; i++)
#pragma unroll
                    for (int j = 0; j < 6; j++) acc[i][j] += hv[i] * wv[j];
            }
            // store partials (only rows that can be valid are ever read)
#pragma unroll
            for (int i = 0; i < 8; i++) {
                float* pr = part + (((size_t)ks * 2 + d) * B + r0 + i) * G3 + c0 + cc;
                *(float2*)&pr[0] = make_float2(acc[i][0], acc[i][1]);
                *(float2*)&pr[2] = make_float2(acc[i][2], acc[i][3]);
                *(float2*)&pr[4] = make_float2(acc[i][4], acc[i][5]);
            }
        }
        grid_sync(bar, NCTA, &gen);

        // phase2: gates + masked update
        for (int it = cta * 256 + tid; it < total; it += nth) {
            int j  = it % H;
            int rr = (it / H) % B;
            int dd = it / (H * B);
            int te = (dd == 0) ? t : (T - 1 - t);
            int bo = perm[rr];
            int valid = te < lenp[rr];
            float hold = hcur[((size_t)dd * B + rr) * H + j];
            float hnew = hold;
            if (valid) {
                float hpr = 0.f, hpz = 0.f, hpn = 0.f;
#pragma unroll
                for (int s = 0; s < KS; s++) {
                    const float* pb = part + (((size_t)s * 2 + dd) * B + rr) * G3;
                    hpr += pb[j]; hpz += pb[H + j]; hpn += pb[2 * H + j];
                }
                const float* bb = b_hh + (size_t)dd * G3;
                hpr += bb[j]; hpz += bb[H + j]; hpn += bb[2 * H + j];
                const float* xr = xp + ((size_t)bo * T + te) * (2 * G3) + (size_t)dd * G3;
                float rg = 1.f / (1.f + expf(-(xr[j] + hpr)));
                float zg = 1.f / (1.f + expf(-(xr[H + j] + hpz)));
                float ng = tanhf(xr[2 * H + j] + rg * hpn);
                hnew = (1.f - zg) * ng + zg * hold;
            }
            hnxt[((size_t)dd * B + rr) * H + j] = hnew;
            out[((size_t)bo * T + te) * (2 * H) + dd * H + j] = valid ? hnew : 0.f;
        }
        grid_sync(bar, NCTA, &gen);
        float* tmp = hcur; hcur = hnxt; hnxt = tmp;
    }
}

// ---------------- segment means over visual_fea ----------------
__global__ __launch_bounds__(256) void seg_mean_kernel(
    const float* __restrict__ vf, const float* __restrict__ loc,
    const int* __restrict__ v_len,
    float* __restrict__ lmean, float* __restrict__ rmean, float* __restrict__ cat)
{
    const int b = blockIdx.x;
    const int col = blockIdx.y * 256 + threadIdx.x;
    const int vl = v_len[b];
    const float scale = (float)(vl - 1);
    const float l0 = loc[b * 2], l1 = loc[b * 2 + 1];
    const int cond = (l0 <= l1);
    const float lhi = cond ? l0 : 0.f;
    const float rlo = cond ? l1 : 1.f;
    const int lend   = (int)floorf(lhi * scale);
    const int rstart = (int)floorf(rlo * scale);
    const int rend   = vl - 1;
    const int ok_l = (0 <= lend);
    const int ok_r = (rstart <= rend);

    float ls = 0.f, rs = 0.f, gs = 0.f;
    for (int t = 0; t < TV; t++) {
        float v = vf[((size_t)b * TV + t) * 1024 + col];
        if (t < vl) gs += v;
        if (ok_l && t <= lend) ls += v;
        if (ok_r && t >= rstart && t <= rend) rs += v;
    }
    float lcnt = ok_l ? (float)(lend + 1) : 1.f;
    float rcnt = ok_r ? (float)(rend - rstart + 1) : 1.f;
    if (lcnt < 1.f) lcnt = 1.f;
    if (rcnt < 1.f) rcnt = 1.f;
    lmean[b * 1024 + col] = ls / lcnt;
    rmean[b * 1024 + col] = rs / rcnt;
    cat[(size_t)b * NCAT + 512 + col] = gs / (float)vl;
}

// ---------------- gather sen_fea ----------------
__global__ void gather_senfea(const float* __restrict__ words,
                              const int* __restrict__ lens,
                              float* __restrict__ out_sf, float* __restrict__ cat)
{
    const int b = blockIdx.x;
    const int t = lens[b] - 1;
    for (int c = threadIdx.x; c < 2 * SHID; c += blockDim.x) {
        float v = words[((size_t)b * TS + t) * (2 * SHID) + c];
        out_sf[(size_t)b * (2 * SHID) + c] = v;
        cat[(size_t)b * NCAT + c] = v;
    }
}

// ---------------- small GEMM with epilogue ----------------
__global__ __launch_bounds__(256) void gemm_small(
    const float* __restrict__ A, const float* __restrict__ W,
    const float* __restrict__ bias, const float* __restrict__ mul, int mulLd,
    float* __restrict__ C, int ldC, int M, int N, int K, int relu)
{
    const int n0 = blockIdx.x * 32, m0 = blockIdx.y * 32;
    __shared__ __align__(16) float As[32][34];
    __shared__ __align__(16) float Wsm[32][34];
    const int tid = threadIdx.x, ty = tid / 16, tx = tid % 16;
    float acc[2][2] = {{0.f, 0.f}, {0.f, 0.f}};

    for (int k0 = 0; k0 < K; k0 += 32) {
        for (int e = tid; e < 1024; e += 256) {
            int r = e / 32, k = e % 32;
            int kg = k0 + k;
            As[k][r]  = (kg < K) ? A[(size_t)(m0 + r) * K + kg] : 0.f;
            Wsm[k][r] = (kg < K) ? W[(size_t)(n0 + r) * K + kg] : 0.f;
        }
        __syncthreads();
#pragma unroll
        for (int k = 0; k < 32; k++) {
            float2 av = *(const float2*)&As[k][ty * 2];
            float2 wv = *(const float2*)&Wsm[k][tx * 2];
            acc[0][0] += av.x * wv.x;  acc[0][1] += av.x * wv.y;
            acc[1][0] += av.y * wv.x;  acc[1][1] += av.y * wv.y;
        }
        __syncthreads();
    }
#pragma unroll
    for (int i = 0; i < 2; i++) {
        int m = m0 + ty * 2 + i;
#pragma unroll
        for (int j = 0; j < 2; j++) {
            int n = n0 + tx * 2 + j;
            float v = acc[i][j] + bias[n];
            if (mul) v *= mul[(size_t)m * mulLd + n];
            if (relu) v = fmaxf(v, 0.f);
            C[(size_t)m * ldC + n] = v;
        }
    }
}

// ---------------- launch ----------------
extern "C" void kernel_launch(void* const* d_in, const int* in_sizes, int n_in,
                              void* d_out, int out_size)
{
    const float* gv     = (const float*)d_in[1];
    const float* sen    = (const float*)d_in[2];
    const float* loc    = (const float*)d_in[5];
    const int*   lens   = (const int*)  d_in[6];
    const int*   v_len  = (const int*)  d_in[7];
    const float* v_w_ih = (const float*)d_in[8];
    const float* v_w_hh = (const float*)d_in[9];
    const float* v_b_ih = (const float*)d_in[10];
    const float* v_b_hh = (const float*)d_in[11];
    const float* s_w_ih = (const float*)d_in[12];
    const float* s_w_hh = (const float*)d_in[13];
    const float* s_b_ih = (const float*)d_in[14];
    const float* s_b_hh = (const float*)d_in[15];
    const float* fc1_w  = (const float*)d_in[16];
    const float* fc1_b  = (const float*)d_in[17];
    const float* fc2_w  = (const float*)d_in[18];
    const float* fc2_b  = (const float*)d_in[19];
    const float* fc3_w  = (const float*)d_in[20];
    const float* fc3_b  = (const float*)d_in[21];
    const float* fc4_w  = (const float*)d_in[22];
    const float* fc4_b  = (const float*)d_in[23];

    float* out    = (float*)d_out;
    float* out_vf = out;
    float* out_sf = out + VF_ELEMS;
    float* out_ft = out + VF_ELEMS + SF_ELEMS;

    float *xp_v, *xp_s, *h_v, *h_s, *part_v, *part_s, *words;
    float *lmean, *rmean, *cat, *sproj;
    int *perm_v, *lenp_v, *perm_s, *lenp_s;
    unsigned* bar;
    cudaGetSymbolAddress((void**)&xp_v,   g_xp_v);
    cudaGetSymbolAddress((void**)&xp_s,   g_xp_s);
    cudaGetSymbolAddress((void**)&h_v,    g_h_v);
    cudaGetSymbolAddress((void**)&h_s,    g_h_s);
    cudaGetSymbolAddress((void**)&part_v, g_part_v);
    cudaGetSymbolAddress((void**)&part_s, g_part_s);
    cudaGetSymbolAddress((void**)&words,  g_words);
    cudaGetSymbolAddress((void**)&lmean,  g_lmean);
    cudaGetSymbolAddress((void**)&rmean,  g_rmean);
    cudaGetSymbolAddress((void**)&cat,    g_cat);
    cudaGetSymbolAddress((void**)&sproj,  g_sproj);
    cudaGetSymbolAddress((void**)&perm_v, g_perm_v);
    cudaGetSymbolAddress((void**)&lenp_v, g_lenp_v);
    cudaGetSymbolAddress((void**)&perm_s, g_perm_s);
    cudaGetSymbolAddress((void**)&lenp_s, g_lenp_s);
    cudaGetSymbolAddress((void**)&bar,    g_bar);

    const int SMEM = (64 * 98 + 64 * 132) * 4;  // 58880 B
    cudaFuncSetAttribute(gru_persistent<512, 1536, 256, 16, 8>,
                         cudaFuncAttributeMaxDynamicSharedMemorySize, SMEM);
    cudaFuncSetAttribute(gru_persistent<256, 768, 40, 8, 4>,
                         cudaFuncAttributeMaxDynamicSharedMemorySize, SMEM);

    // 1. sort batches by length + zero barriers; zero hidden states
    sort_init_kernel<<<1, 128>>>(v_len, lens, perm_v, lenp_v, perm_s, lenp_s, bar);
    zero_h_kernel<<<(2*2*B*VHID + 255) / 256, 256>>>(h_v, h_s);

    // 2. input projections (masked-row tile skip)
    gemm_bias<<<dim3(3072/128, (B*TV)/128), 256>>>(gv,  v_w_ih, v_b_ih, xp_v,
                                                   B*TV, 3072, VIN, v_len, TV);
    gemm_bias<<<dim3(1536/128, (B*TS)/128), 256>>>(sen, s_w_ih, s_b_ih, xp_s,
                                                   B*TS, 1536, SIN, lens, TS);

    // 3. persistent visual GRU (2*16*8 = 256 CTAs)
    gru_persistent<512, 1536, 256, 16, 8><<<256, 256, SMEM>>>(
        xp_v, v_w_hh, v_b_hh, h_v, part_v, out_vf, perm_v, lenp_v, bar);

    // 4. persistent sentence GRU (2*8*4 = 64 CTAs)
    gru_persistent<256, 768, 40, 8, 4><<<64, 256, SMEM>>>(
        xp_s, s_w_hh, s_b_hh, h_s, part_s, words, perm_s, lenp_s, bar + 2);

    // 5. sen_fea gather
    gather_senfea<<<B, 256>>>(words, lens, out_sf, cat);

    // 6. segment means + global mean
    seg_mean_kernel<<<dim3(B, 4), 256>>>(out_vf, loc, v_len, lmean, rmean, cat);

    // 7. FC stack
    gemm_small<<<dim3(LCROSS/32, B/32), 256>>>(out_sf, fc2_w, fc2_b, nullptr, 0,
                                               sproj, LCROSS, B, LCROSS, 2*SHID, 0);
    gemm_small<<<dim3(LCROSS/32, B/32), 256>>>(lmean, fc1_w, fc1_b, sproj, LCROSS,
                                               cat + 1536, NCAT, B, LCROSS, 2*VHID, 1);
    gemm_small<<<dim3(LCROSS/32, B/32), 256>>>(rmean, fc1_w, fc1_b, sproj, LCROSS,
                                               cat + 2048, NCAT, B, LCROSS, 2*VHID, 1);
    gemm_small<<<dim3(NLOC/32, B/32), 256>>>(loc, fc3_w, fc3_b, nullptr, 0,
                                             cat + 2560, NCAT, B, NLOC, 2, 1);
    gemm_small<<<dim3(NFEAT/32, B/32), 256>>>(cat, fc4_w, fc4_b, nullptr, 0,
                                              out_ft, NFEAT, B, NFEAT, NCAT, 1);
}

// round 4
// speedup vs baseline: 1.6969x; 1.0156x over previous
#include <cuda_runtime.h>
#include <math.h>
#include <stdint.h>

// ---------------- problem constants ----------------
#define B        128
#define TV       256
#define TS       40
#define VIN      1024
#define VHID     512
#define SIN      300
#define SHID     256
#define NCAT     2624
#define NFEAT    1024
#define LCROSS   512
#define NLOC     64

#define VF_ELEMS   ((size_t)B*TV*2*VHID)
#define SF_ELEMS   ((size_t)B*2*SHID)

// ---------------- scratch (__device__ globals) ----------------
__device__ float g_xp_v[(size_t)B*TV*3072];
__device__ float g_xp_s[(size_t)B*TS*1536];
__device__ float g_h_v[2*2*B*VHID];
__device__ float g_h_s[2*2*B*SHID];
__device__ float g_part_v[8*2*B*1536];
__device__ float g_part_s[4*2*B*768];
__device__ float g_words[(size_t)B*TS*2*SHID];
__device__ float g_lmean[B*1024];
__device__ float g_rmean[B*1024];
__device__ float g_cat[B*NCAT];
__device__ float g_sproj[B*LCROSS];
__device__ int   g_perm_v[B], g_lenp_v[B];
__device__ int   g_perm_s[B], g_lenp_s[B];
__device__ unsigned g_bar[4];

// ---------------- init ----------------
__global__ void sort_init_kernel(const int* __restrict__ v_len,
                                 const int* __restrict__ lens,
                                 int* pv, int* lv, int* ps, int* ls,
                                 unsigned* bar)
{
    int i = threadIdx.x;
    if (i < 4) bar[i] = 0u;
    int a = v_len[i], rank = 0;
    for (int j = 0; j < B; j++) {
        int c = v_len[j];
        rank += (c > a) || (c == a && j < i);
    }
    pv[rank] = i; lv[rank] = a;
    a = lens[i]; rank = 0;
    for (int j = 0; j < B; j++) {
        int c = lens[j];
        rank += (c > a) || (c == a && j < i);
    }
    ps[rank] = i; ls[rank] = a;
}

__global__ void zero_h_kernel(float* hv, float* hs) {
    int i = blockIdx.x * blockDim.x + threadIdx.x;
    if (i < 2*2*B*VHID) hv[i] = 0.f;
    if (i < 2*2*B*SHID) hs[i] = 0.f;
}

// ---------------- tf32 helpers ----------------
__device__ __forceinline__ uint32_t tf32_rna(float x) {
    uint32_t r;
    asm("cvt.rna.tf32.f32 %0, %1;" : "=r"(r) : "f"(x));
    return r;
}
__device__ __forceinline__ void mma_tf32(float* d, const uint32_t* a, const uint32_t* b) {
    asm volatile(
        "mma.sync.aligned.m16n8k8.row.col.f32.tf32.tf32.f32 "
        "{%0,%1,%2,%3}, {%4,%5,%6,%7}, {%8,%9}, {%0,%1,%2,%3};"
        : "+f"(d[0]), "+f"(d[1]), "+f"(d[2]), "+f"(d[3])
        : "r"(a[0]), "r"(a[1]), "r"(a[2]), "r"(a[3]), "r"(b[0]), "r"(b[1]));
}

// ---------------- tensor-core GEMM: C[M,N] = A[M,K] @ W[N,K]^T + bias ------
// 3xTF32 split (Ah*Wh + Al*Wh + Ah*Wl) -> ~fp32 accuracy on tensor pipe.
// 128x128 tile, BK=16, 8 warps (2x4), warp tile 64x32 = 4x4 m16n8k8 frags.
// Per-tile row-validity skip as before.
__global__ __launch_bounds__(256) void gemm_tf32(
    const float* __restrict__ A, const float* __restrict__ W,
    const float* __restrict__ bias, float* __restrict__ C,
    int M, int N, int K, const int* __restrict__ lens, int T)
{
    const int n0 = blockIdx.x * 128;
    const int m0 = blockIdx.y * 128;
    const int tid = threadIdx.x;

    __shared__ uint32_t Ah[16][132], Al[16][132];
    __shared__ uint32_t Wh[16][132], Wl[16][132];
    __shared__ int s_any;

    if (lens) {
        if (tid == 0) {
            int any = 0;
            for (int r = 0; r < 128; r++) {
                int row = m0 + r;
                if (row % T < lens[row / T]) { any = 1; break; }
            }
            s_any = any;
        }
        __syncthreads();
        if (!s_any) return;
    }

    const int wid  = tid / 32, lane = tid % 32;
    const int wm   = (wid / 4) * 64;      // warp row offset in tile
    const int wn   = (wid % 4) * 32;      // warp col offset in tile
    const int gid  = lane >> 2, tig = lane & 3;

    float acc[4][4][4];
#pragma unroll
    for (int i = 0; i < 4; i++)
#pragma unroll
        for (int j = 0; j < 4; j++)
#pragma unroll
            for (int c = 0; c < 4; c++) acc[i][j][c] = 0.f;

    for (int k0 = 0; k0 < K; k0 += 16) {
        __syncthreads();
        // stage A and W tiles, split hi/lo
        for (int e = tid; e < 2048; e += 256) {
            int r = e / 16, kk = e % 16;
            int kg = k0 + kk;
            float av = (kg < K) ? A[(size_t)(m0 + r) * K + kg] : 0.f;
            float wv = (kg < K) ? W[(size_t)(n0 + r) * K + kg] : 0.f;
            uint32_t ah = tf32_rna(av);
            uint32_t wh = tf32_rna(wv);
            Ah[kk][r] = ah; Al[kk][r] = tf32_rna(av - __uint_as_float(ah));
            Wh[kk][r] = wh; Wl[kk][r] = tf32_rna(wv - __uint_as_float(wh));
        }
        __syncthreads();

#pragma unroll
        for (int ks = 0; ks < 2; ks++) {
            const int kb = ks * 8;
            uint32_t bh[4][2], bl[4][2];
#pragma unroll
            for (int j = 0; j < 4; j++) {
                int nc = wn + j * 8 + gid;
                bh[j][0] = Wh[kb + tig][nc];     bh[j][1] = Wh[kb + tig + 4][nc];
                bl[j][0] = Wl[kb + tig][nc];     bl[j][1] = Wl[kb + tig + 4][nc];
            }
#pragma unroll
            for (int i = 0; i < 4; i++) {
                int mr = wm + i * 16 + gid;
                uint32_t ah[4], al[4];
                ah[0] = Ah[kb + tig][mr];        ah[1] = Ah[kb + tig][mr + 8];
                ah[2] = Ah[kb + tig + 4][mr];    ah[3] = Ah[kb + tig + 4][mr + 8];
                al[0] = Al[kb + tig][mr];        al[1] = Al[kb + tig][mr + 8];
                al[2] = Al[kb + tig + 4][mr];    al[3] = Al[kb + tig + 4][mr + 8];
#pragma unroll
                for (int j = 0; j < 4; j++) {
                    mma_tf32(acc[i][j], ah, bh[j]);
                    mma_tf32(acc[i][j], al, bh[j]);
                    mma_tf32(acc[i][j], ah, bl[j]);
                }
            }
        }
    }

    // epilogue: bias + store (float2 per fragment row)
#pragma unroll
    for (int i = 0; i < 4; i++) {
#pragma unroll
        for (int j = 0; j < 4; j++) {
            int col = n0 + wn + j * 8 + tig * 2;
            float b0 = bias[col], b1 = bias[col + 1];
            int r0g = m0 + wm + i * 16 + gid;
            *(float2*)&C[(size_t)r0g * N + col] =
                make_float2(acc[i][j][0] + b0, acc[i][j][1] + b1);
            *(float2*)&C[(size_t)(r0g + 8) * N + col] =
                make_float2(acc[i][j][2] + b0, acc[i][j][3] + b1);
        }
    }
}

// ---------------- software grid barrier ----------------
__device__ __forceinline__ void grid_sync(unsigned* bar, int ncta, unsigned* gen)
{
    __syncthreads();
    if (threadIdx.x == 0) {
        unsigned target = *gen + 1u;
        __threadfence();
        unsigned arr = atomicAdd(&bar[0], 1u);
        if (arr == (unsigned)(ncta - 1)) {
            atomicExch(&bar[0], 0u);
            __threadfence();
            atomicExch(&bar[1], target);
        } else {
            while (atomicAdd(&bar[1], 0u) < target) __nanosleep(64);
        }
        __threadfence();
        *gen = target;
    }
    __syncthreads();
}

// ---------------- persistent weight-stationary bidirectional GRU ----------
template<int H, int G3, int T, int NCT, int KS>
__global__ __launch_bounds__(256) void gru_persistent(
    const float* __restrict__ xp, const float* __restrict__ w_hh,
    const float* __restrict__ b_hh, float* __restrict__ hbuf,
    float* __restrict__ part, float* __restrict__ out,
    const int* __restrict__ perm, const int* __restrict__ lenp,
    unsigned* __restrict__ bar)
{
    constexpr int KC = 64;
    constexpr int NCTA = 2 * NCT * KS;
    extern __shared__ float sm[];
    float* Ws = sm;                        // [KC][98]
    float* Hs = sm + KC * 98;              // [KC][132]

    const int cta = blockIdx.x;
    const int d   = cta / (NCT * KS);
    const int ct  = (cta % (NCT * KS)) / KS;
    const int ks  = cta % KS;
    const int c0  = ct * 96;
    const int k0  = ks * KC;
    const int tid = threadIdx.x;
    const int ty  = tid / 16, tx = tid % 16;
    const int r0  = ty * 8, cc = tx * 6;

    for (int e = tid; e < KC * 96; e += 256) {
        int k = e % KC, c = e / KC;
        Ws[k * 98 + c] = w_hh[((size_t)d * G3 + c0 + c) * H + k0 + k];
    }

    const int myLen = lenp[r0];
    unsigned gen = 0;
    float* hcur = hbuf;
    float* hnxt = hbuf + 2 * B * H;
    const int total = 2 * B * H;
    const int nth   = NCTA * 256;

    for (int t = 0; t < T; t++) {
        const int te1 = (d == 0) ? t : (T - 1 - t);

        for (int e = tid; e < KC * B; e += 256) {
            int k = e % KC, r = e / KC;
            Hs[k * 132 + r] = hcur[((size_t)d * B + r) * H + k0 + k];
        }
        __syncthreads();

        if (te1 < myLen) {
            float acc[8][6];
#pragma unroll
            for (int i = 0; i < 8; i++)
#pragma unroll
                for (int j = 0; j < 6; j++) acc[i][j] = 0.f;
#pragma unroll 4
            for (int k = 0; k < KC; k++) {
                float hv[8], wv[6];
                *(float4*)&hv[0] = *(const float4*)&Hs[k * 132 + r0];
                *(float4*)&hv[4] = *(const float4*)&Hs[k * 132 + r0 + 4];
                *(float2*)&wv[0] = *(const float2*)&Ws[k * 98 + cc];
                *(float2*)&wv[2] = *(const float2*)&Ws[k * 98 + cc + 2];
                *(float2*)&wv[4] = *(const float2*)&Ws[k * 98 + cc + 4];
#pragma unroll
                for (int i = 0; i < 8; i++)
#pragma unroll
                    for (int j = 0; j < 6; j++) acc[i][j] += hv[i] * wv[j];
            }
#pragma unroll
            for (int i = 0; i < 8; i++) {
                float* pr = part + (((size_t)ks * 2 + d) * B + r0 + i) * G3 + c0 + cc;
                *(float2*)&pr[0] = make_float2(acc[i][0], acc[i][1]);
                *(float2*)&pr[2] = make_float2(acc[i][2], acc[i][3]);
                *(float2*)&pr[4] = make_float2(acc[i][4], acc[i][5]);
            }
        }
        grid_sync(bar, NCTA, &gen);

        for (int it = cta * 256 + tid; it < total; it += nth) {
            int j  = it % H;
            int rr = (it / H) % B;
            int dd = it / (H * B);
            int te = (dd == 0) ? t : (T - 1 - t);
            int bo = perm[rr];
            int valid = te < lenp[rr];
            float hold = hcur[((size_t)dd * B + rr) * H + j];
            float hnew = hold;
            if (valid) {
                float hpr = 0.f, hpz = 0.f, hpn = 0.f;
#pragma unroll
                for (int s = 0; s < KS; s++) {
                    const float* pb = part + (((size_t)s * 2 + dd) * B + rr) * G3;
                    hpr += pb[j]; hpz += pb[H + j]; hpn += pb[2 * H + j];
                }
                const float* bb = b_hh + (size_t)dd * G3;
                hpr += bb[j]; hpz += bb[H + j]; hpn += bb[2 * H + j];
                const float* xr = xp + ((size_t)bo * T + te) * (2 * G3) + (size_t)dd * G3;
                float rg = 1.f / (1.f + expf(-(xr[j] + hpr)));
                float zg = 1.f / (1.f + expf(-(xr[H + j] + hpz)));
                float ng = tanhf(xr[2 * H + j] + rg * hpn);
                hnew = (1.f - zg) * ng + zg * hold;
            }
            hnxt[((size_t)dd * B + rr) * H + j] = hnew;
            out[((size_t)bo * T + te) * (2 * H) + dd * H + j] = valid ? hnew : 0.f;
        }
        grid_sync(bar, NCTA, &gen);
        float* tmp = hcur; hcur = hnxt; hnxt = tmp;
    }
}

// ---------------- segment means ----------------
__global__ __launch_bounds__(256) void seg_mean_kernel(
    const float* __restrict__ vf, const float* __restrict__ loc,
    const int* __restrict__ v_len,
    float* __restrict__ lmean, float* __restrict__ rmean, float* __restrict__ cat)
{
    const int b = blockIdx.x;
    const int col = blockIdx.y * 256 + threadIdx.x;
    const int vl = v_len[b];
    const float scale = (float)(vl - 1);
    const float l0 = loc[b * 2], l1 = loc[b * 2 + 1];
    const int cond = (l0 <= l1);
    const float lhi = cond ? l0 : 0.f;
    const float rlo = cond ? l1 : 1.f;
    const int lend   = (int)floorf(lhi * scale);
    const int rstart = (int)floorf(rlo * scale);
    const int rend   = vl - 1;
    const int ok_l = (0 <= lend);
    const int ok_r = (rstart <= rend);

    float ls = 0.f, rs = 0.f, gs = 0.f;
    for (int t = 0; t < TV; t++) {
        float v = vf[((size_t)b * TV + t) * 1024 + col];
        if (t < vl) gs += v;
        if (ok_l && t <= lend) ls += v;
        if (ok_r && t >= rstart && t <= rend) rs += v;
    }
    float lcnt = ok_l ? (float)(lend + 1) : 1.f;
    float rcnt = ok_r ? (float)(rend - rstart + 1) : 1.f;
    if (lcnt < 1.f) lcnt = 1.f;
    if (rcnt < 1.f) rcnt = 1.f;
    lmean[b * 1024 + col] = ls / lcnt;
    rmean[b * 1024 + col] = rs / rcnt;
    cat[(size_t)b * NCAT + 512 + col] = gs / (float)vl;
}

// ---------------- gather sen_fea ----------------
__global__ void gather_senfea(const float* __restrict__ words,
                              const int* __restrict__ lens,
                              float* __restrict__ out_sf, float* __restrict__ cat)
{
    const int b = blockIdx.x;
    const int t = lens[b] - 1;
    for (int c = threadIdx.x; c < 2 * SHID; c += blockDim.x) {
        float v = words[((size_t)b * TS + t) * (2 * SHID) + c];
        out_sf[(size_t)b * (2 * SHID) + c] = v;
        cat[(size_t)b * NCAT + c] = v;
    }
}

// ---------------- small GEMM with epilogue ----------------
__global__ __launch_bounds__(256) void gemm_small(
    const float* __restrict__ A, const float* __restrict__ W,
    const float* __restrict__ bias, const float* __restrict__ mul, int mulLd,
    float* __restrict__ C, int ldC, int M, int N, int K, int relu)
{
    const int n0 = blockIdx.x * 32, m0 = blockIdx.y * 32;
    __shared__ __align__(16) float As[32][34];
    __shared__ __align__(16) float Wsm[32][34];
    const int tid = threadIdx.x, ty = tid / 16, tx = tid % 16;
    float acc[2][2] = {{0.f, 0.f}, {0.f, 0.f}};

    for (int k0 = 0; k0 < K; k0 += 32) {
        for (int e = tid; e < 1024; e += 256) {
            int r = e / 32, k = e % 32;
            int kg = k0 + k;
            As[k][r]  = (kg < K) ? A[(size_t)(m0 + r) * K + kg] : 0.f;
            Wsm[k][r] = (kg < K) ? W[(size_t)(n0 + r) * K + kg] : 0.f;
        }
        __syncthreads();
#pragma unroll
        for (int k = 0; k < 32; k++) {
            float2 av = *(const float2*)&As[k][ty * 2];
            float2 wv = *(const float2*)&Wsm[k][tx * 2];
            acc[0][0] += av.x * wv.x;  acc[0][1] += av.x * wv.y;
            acc[1][0] += av.y * wv.x;  acc[1][1] += av.y * wv.y;
        }
        __syncthreads();
    }
#pragma unroll
    for (int i = 0; i < 2; i++) {
        int m = m0 + ty * 2 + i;
#pragma unroll
        for (int j = 0; j < 2; j++) {
            int n = n0 + tx * 2 + j;
            float v = acc[i][j] + bias[n];
            if (mul) v *= mul[(size_t)m * mulLd + n];
            if (relu) v = fmaxf(v, 0.f);
            C[(size_t)m * ldC + n] = v;
        }
    }
}

// ---------------- launch ----------------
extern "C" void kernel_launch(void* const* d_in, const int* in_sizes, int n_in,
                              void* d_out, int out_size)
{
    const float* gv     = (const float*)d_in[1];
    const float* sen    = (const float*)d_in[2];
    const float* loc    = (const float*)d_in[5];
    const int*   lens   = (const int*)  d_in[6];
    const int*   v_len  = (const int*)  d_in[7];
    const float* v_w_ih = (const float*)d_in[8];
    const float* v_w_hh = (const float*)d_in[9];
    const float* v_b_ih = (const float*)d_in[10];
    const float* v_b_hh = (const float*)d_in[11];
    const float* s_w_ih = (const float*)d_in[12];
    const float* s_w_hh = (const float*)d_in[13];
    const float* s_b_ih = (const float*)d_in[14];
    const float* s_b_hh = (const float*)d_in[15];
    const float* fc1_w  = (const float*)d_in[16];
    const float* fc1_b  = (const float*)d_in[17];
    const float* fc2_w  = (const float*)d_in[18];
    const float* fc2_b  = (const float*)d_in[19];
    const float* fc3_w  = (const float*)d_in[20];
    const float* fc3_b  = (const float*)d_in[21];
    const float* fc4_w  = (const float*)d_in[22];
    const float* fc4_b  = (const float*)d_in[23];

    float* out    = (float*)d_out;
    float* out_vf = out;
    float* out_sf = out + VF_ELEMS;
    float* out_ft = out + VF_ELEMS + SF_ELEMS;

    float *xp_v, *xp_s, *h_v, *h_s, *part_v, *part_s, *words;
    float *lmean, *rmean, *cat, *sproj;
    int *perm_v, *lenp_v, *perm_s, *lenp_s;
    unsigned* bar;
    cudaGetSymbolAddress((void**)&xp_v,   g_xp_v);
    cudaGetSymbolAddress((void**)&xp_s,   g_xp_s);
    cudaGetSymbolAddress((void**)&h_v,    g_h_v);
    cudaGetSymbolAddress((void**)&h_s,    g_h_s);
    cudaGetSymbolAddress((void**)&part_v, g_part_v);
    cudaGetSymbolAddress((void**)&part_s, g_part_s);
    cudaGetSymbolAddress((void**)&words,  g_words);
    cudaGetSymbolAddress((void**)&lmean,  g_lmean);
    cudaGetSymbolAddress((void**)&rmean,  g_rmean);
    cudaGetSymbolAddress((void**)&cat,    g_cat);
    cudaGetSymbolAddress((void**)&sproj,  g_sproj);
    cudaGetSymbolAddress((void**)&perm_v, g_perm_v);
    cudaGetSymbolAddress((void**)&lenp_v, g_lenp_v);
    cudaGetSymbolAddress((void**)&perm_s, g_perm_s);
    cudaGetSymbolAddress((void**)&lenp_s, g_lenp_s);
    cudaGetSymbolAddress((void**)&bar,    g_bar);

    const int SMEM = (64 * 98 + 64 * 132) * 4;
    cudaFuncSetAttribute(gru_persistent<512, 1536, 256, 16, 8>,
                         cudaFuncAttributeMaxDynamicSharedMemorySize, SMEM);
    cudaFuncSetAttribute(gru_persistent<256, 768, 40, 8, 4>,
                         cudaFuncAttributeMaxDynamicSharedMemorySize, SMEM);

    // 1. sort + zero
    sort_init_kernel<<<1, 128>>>(v_len, lens, perm_v, lenp_v, perm_s, lenp_s, bar);
    zero_h_kernel<<<(2*2*B*VHID + 255) / 256, 256>>>(h_v, h_s);

    // 2. input projections on tensor cores (3xTF32)
    gemm_tf32<<<dim3(3072/128, (B*TV)/128), 256>>>(gv,  v_w_ih, v_b_ih, xp_v,
                                                   B*TV, 3072, VIN, v_len, TV);
    gemm_tf32<<<dim3(1536/128, (B*TS)/128), 256>>>(sen, s_w_ih, s_b_ih, xp_s,
                                                   B*TS, 1536, SIN, lens, TS);

    // 3. persistent visual GRU
    gru_persistent<512, 1536, 256, 16, 8><<<256, 256, SMEM>>>(
        xp_v, v_w_hh, v_b_hh, h_v, part_v, out_vf, perm_v, lenp_v, bar);

    // 4. persistent sentence GRU
    gru_persistent<256, 768, 40, 8, 4><<<64, 256, SMEM>>>(
        xp_s, s_w_hh, s_b_hh, h_s, part_s, words, perm_s, lenp_s, bar + 2);

    // 5. sen_fea gather
    gather_senfea<<<B, 256>>>(words, lens, out_sf, cat);

    // 6. segment means + global mean
    seg_mean_kernel<<<dim3(B, 4), 256>>>(out_vf, loc, v_len, lmean, rmean, cat);

    // 7. FC stack
    gemm_small<<<dim3(LCROSS/32, B/32), 256>>>(out_sf, fc2_w, fc2_b, nullptr, 0,
                                               sproj, LCROSS, B, LCROSS, 2*SHID, 0);
    gemm_small<<<dim3(LCROSS/32, B/32), 256>>>(lmean, fc1_w, fc1_b, sproj, LCROSS,
                                               cat + 1536, NCAT, B, LCROSS, 2*VHID, 1);
    gemm_small<<<dim3(LCROSS/32, B/32), 256>>>(rmean, fc1_w, fc1_b, sproj, LCROSS,
                                               cat + 2048, NCAT, B, LCROSS, 2*VHID, 1);
    gemm_small<<<dim3(NLOC/32, B/32), 256>>>(loc, fc3_w, fc3_b, nullptr, 0,
                                             cat + 2560, NCAT, B, NLOC, 2, 1);
    gemm_small<<<dim3(NFEAT/32, B/32), 256>>>(cat, fc4_w, fc4_b, nullptr, 0,
                                              out_ft, NFEAT, B, NFEAT, NCAT, 1);
}

// round 5
// speedup vs baseline: 1.7599x; 1.0371x over previous
#include <cuda_runtime.h>
#include <math.h>
#include <stdint.h>

// ---------------- problem constants ----------------
#define B        128
#define TV       256
#define TS       40
#define VIN      1024
#define VHID     512
#define SIN      300
#define SHID     256
#define NCAT     2624
#define NFEAT    1024
#define LCROSS   512
#define NLOC     64

#define VF_ELEMS   ((size_t)B*TV*2*VHID)
#define SF_ELEMS   ((size_t)B*2*SHID)

// ---------------- scratch (__device__ globals) ----------------
__device__ float g_xp_v[(size_t)B*TV*3072];
__device__ float g_xp_s[(size_t)B*TS*1536];
__device__ float g_h_v[2*2*B*VHID];
__device__ float g_h_s[2*2*B*SHID];
__device__ float g_part_v[8*2*B*1536];
__device__ float g_part_s[4*2*B*768];
__device__ float g_words[(size_t)B*TS*2*SHID];
__device__ float g_lmean[B*1024];
__device__ float g_rmean[B*1024];
__device__ float g_cat[B*NCAT];
__device__ float g_sproj[B*LCROSS];
__device__ int   g_perm_v[B], g_lenp_v[B];
__device__ int   g_perm_s[B], g_lenp_s[B];
__device__ unsigned g_bar[4];

// ---------------- init ----------------
__global__ void sort_init_kernel(const int* __restrict__ v_len,
                                 const int* __restrict__ lens,
                                 int* pv, int* lv, int* ps, int* ls,
                                 unsigned* bar)
{
    int i = threadIdx.x;
    if (i < 4) bar[i] = 0u;
    int a = v_len[i], rank = 0;
    for (int j = 0; j < B; j++) {
        int c = v_len[j];
        rank += (c > a) || (c == a && j < i);
    }
    pv[rank] = i; lv[rank] = a;
    a = lens[i]; rank = 0;
    for (int j = 0; j < B; j++) {
        int c = lens[j];
        rank += (c > a) || (c == a && j < i);
    }
    ps[rank] = i; ls[rank] = a;
}

__global__ void zero_h_kernel(float* hv, float* hs) {
    int i = blockIdx.x * blockDim.x + threadIdx.x;
    if (i < 2*2*B*VHID) hv[i] = 0.f;
    if (i < 2*2*B*SHID) hs[i] = 0.f;
}

// ---------------- tf32 helpers ----------------
__device__ __forceinline__ uint32_t tf32_rna(float x) {
    uint32_t r;
    asm("cvt.rna.tf32.f32 %0, %1;" : "=r"(r) : "f"(x));
    return r;
}
__device__ __forceinline__ void mma_tf32(float* d, const uint32_t* a, const uint32_t* b) {
    asm volatile(
        "mma.sync.aligned.m16n8k8.row.col.f32.tf32.tf32.f32 "
        "{%0,%1,%2,%3}, {%4,%5,%6,%7}, {%8,%9}, {%0,%1,%2,%3};"
        : "+f"(d[0]), "+f"(d[1]), "+f"(d[2]), "+f"(d[3])
        : "r"(a[0]), "r"(a[1]), "r"(a[2]), "r"(a[3]), "r"(b[0]), "r"(b[1]));
}

// ---------------- tensor-core GEMM (input projections) ----------------
__global__ __launch_bounds__(256) void gemm_tf32(
    const float* __restrict__ A, const float* __restrict__ W,
    const float* __restrict__ bias, float* __restrict__ C,
    int M, int N, int K, const int* __restrict__ lens, int T)
{
    const int n0 = blockIdx.x * 128;
    const int m0 = blockIdx.y * 128;
    const int tid = threadIdx.x;

    __shared__ uint32_t Ah[16][132], Al[16][132];
    __shared__ uint32_t Wh[16][132], Wl[16][132];
    __shared__ int s_any;

    if (lens) {
        if (tid == 0) {
            int any = 0;
            for (int r = 0; r < 128; r++) {
                int row = m0 + r;
                if (row % T < lens[row / T]) { any = 1; break; }
            }
            s_any = any;
        }
        __syncthreads();
        if (!s_any) return;
    }

    const int wid  = tid / 32, lane = tid % 32;
    const int wm   = (wid / 4) * 64;
    const int wn   = (wid % 4) * 32;
    const int gid  = lane >> 2, tig = lane & 3;

    float acc[4][4][4];
#pragma unroll
    for (int i = 0; i < 4; i++)
#pragma unroll
        for (int j = 0; j < 4; j++)
#pragma unroll
            for (int c = 0; c < 4; c++) acc[i][j][c] = 0.f;

    for (int k0 = 0; k0 < K; k0 += 16) {
        __syncthreads();
        for (int e = tid; e < 2048; e += 256) {
            int r = e / 16, kk = e % 16;
            int kg = k0 + kk;
            float av = (kg < K) ? A[(size_t)(m0 + r) * K + kg] : 0.f;
            float wv = (kg < K) ? W[(size_t)(n0 + r) * K + kg] : 0.f;
            uint32_t ah = tf32_rna(av);
            uint32_t wh = tf32_rna(wv);
            Ah[kk][r] = ah; Al[kk][r] = tf32_rna(av - __uint_as_float(ah));
            Wh[kk][r] = wh; Wl[kk][r] = tf32_rna(wv - __uint_as_float(wh));
        }
        __syncthreads();

#pragma unroll
        for (int ks = 0; ks < 2; ks++) {
            const int kb = ks * 8;
            uint32_t bh[4][2], bl[4][2];
#pragma unroll
            for (int j = 0; j < 4; j++) {
                int nc = wn + j * 8 + gid;
                bh[j][0] = Wh[kb + tig][nc];     bh[j][1] = Wh[kb + tig + 4][nc];
                bl[j][0] = Wl[kb + tig][nc];     bl[j][1] = Wl[kb + tig + 4][nc];
            }
#pragma unroll
            for (int i = 0; i < 4; i++) {
                int mr = wm + i * 16 + gid;
                uint32_t ah[4], al[4];
                ah[0] = Ah[kb + tig][mr];        ah[1] = Ah[kb + tig][mr + 8];
                ah[2] = Ah[kb + tig + 4][mr];    ah[3] = Ah[kb + tig + 4][mr + 8];
                al[0] = Al[kb + tig][mr];        al[1] = Al[kb + tig][mr + 8];
                al[2] = Al[kb + tig + 4][mr];    al[3] = Al[kb + tig + 4][mr + 8];
#pragma unroll
                for (int j = 0; j < 4; j++) {
                    mma_tf32(acc[i][j], ah, bh[j]);
                    mma_tf32(acc[i][j], al, bh[j]);
                    mma_tf32(acc[i][j], ah, bl[j]);
                }
            }
        }
    }

#pragma unroll
    for (int i = 0; i < 4; i++) {
#pragma unroll
        for (int j = 0; j < 4; j++) {
            int col = n0 + wn + j * 8 + tig * 2;
            float b0 = bias[col], b1 = bias[col + 1];
            int r0g = m0 + wm + i * 16 + gid;
            *(float2*)&C[(size_t)r0g * N + col] =
                make_float2(acc[i][j][0] + b0, acc[i][j][1] + b1);
            *(float2*)&C[(size_t)(r0g + 8) * N + col] =
                make_float2(acc[i][j][2] + b0, acc[i][j][3] + b1);
        }
    }
}

// ---------------- software grid barrier (volatile-load poll) ----------------
__device__ __forceinline__ void grid_sync(unsigned* bar, int ncta, unsigned* gen)
{
    __syncthreads();
    if (threadIdx.x == 0) {
        unsigned target = *gen + 1u;
        __threadfence();
        unsigned arr = atomicAdd(&bar[0], 1u);
        if (arr == (unsigned)(ncta - 1)) {
            atomicExch(&bar[0], 0u);
            __threadfence();
            atomicExch(&bar[1], target);
        } else {
            while (*(volatile unsigned*)&bar[1] < target) { }
        }
        __threadfence();
        *gen = target;
    }
    __syncthreads();
}

// ---------------- persistent weight-stationary GRU, tensor-core phase1 ------
// Grid: 2(dir)*NCT(96-col tiles over 3H)*KS(64-K slices). 256 thr, 8 warps.
// Phase1 (per step): hp partials = h @ W^T via 3xTF32 m16n8k8; warp tile 32x48.
// W hi/lo tf32 split precomputed in smem (stationary); h converted in regs.
// Phase2: reduce partials over KS + bias + gates + masked update.
template<int H, int G3, int T, int NCT, int KS>
__global__ __launch_bounds__(256, 2) void gru_persistent(
    const float* __restrict__ xp, const float* __restrict__ w_hh,
    const float* __restrict__ b_hh, float* __restrict__ hbuf,
    float* __restrict__ part, float* __restrict__ out,
    const int* __restrict__ perm, const int* __restrict__ lenp,
    unsigned* __restrict__ bar)
{
    constexpr int KC = 64;
    constexpr int NCTA = 2 * NCT * KS;
    extern __shared__ float sm[];
    uint32_t* Wh = (uint32_t*)sm;             // [KC][98]
    uint32_t* Wl = Wh + KC * 98;              // [KC][98]
    float*    Hs = (float*)(Wl + KC * 98);    // [KC][132]

    const int cta = blockIdx.x;
    const int d   = cta / (NCT * KS);
    const int ct  = (cta % (NCT * KS)) / KS;
    const int ks  = cta % KS;
    const int c0  = ct * 96;
    const int k0  = ks * KC;
    const int tid = threadIdx.x;
    const int wid = tid / 32, lane = tid % 32;
    const int gid = lane >> 2, tig = lane & 3;
    const int wm  = (wid >> 1) * 32;          // warp row offset (0..96)
    const int wn  = (wid & 1) * 48;           // warp col offset (0/48)

    // stationary W tile, tf32 hi/lo: W[k][c] = w_hh[d][c0+c][k0+k]
    for (int e = tid; e < KC * 96; e += 256) {
        int k = e % KC, c = e / KC;
        float w = w_hh[((size_t)d * G3 + c0 + c) * H + k0 + k];
        uint32_t wh = tf32_rna(w);
        Wh[k * 98 + c] = wh;
        Wl[k * 98 + c] = tf32_rna(w - __uint_as_float(wh));
    }

    const int myLen = lenp[wm];               // rows sorted desc: max in warp tile
    unsigned gen = 0;
    float* hcur = hbuf;
    float* hnxt = hbuf + 2 * B * H;
    const int total = 2 * B * H;
    const int nth   = NCTA * 256;

    for (int t = 0; t < T; t++) {
        const int te1 = (d == 0) ? t : (T - 1 - t);

        // stage h slice (fp32): Hs[k][r] = hcur[d][r][k0+k]
        for (int e = tid; e < KC * B; e += 256) {
            int k = e % KC, r = e / KC;
            Hs[k * 132 + r] = hcur[((size_t)d * B + r) * H + k0 + k];
        }
        __syncthreads();

        if (te1 < myLen) {
            float acc[2][6][4];
#pragma unroll
            for (int i = 0; i < 2; i++)
#pragma unroll
                for (int j = 0; j < 6; j++)
#pragma unroll
                    for (int c = 0; c < 4; c++) acc[i][j][c] = 0.f;

#pragma unroll
            for (int k8 = 0; k8 < KC / 8; k8++) {
                const int kb = k8 * 8;
                uint32_t bh[6][2], bl[6][2];
#pragma unroll
                for (int j = 0; j < 6; j++) {
                    int c = wn + j * 8 + gid;
                    bh[j][0] = Wh[(kb + tig) * 98 + c];
                    bh[j][1] = Wh[(kb + tig + 4) * 98 + c];
                    bl[j][0] = Wl[(kb + tig) * 98 + c];
                    bl[j][1] = Wl[(kb + tig + 4) * 98 + c];
                }
#pragma unroll
                for (int mi = 0; mi < 2; mi++) {
                    int r = wm + mi * 16 + gid;
                    float h0 = Hs[(kb + tig) * 132 + r];
                    float h1 = Hs[(kb + tig) * 132 + r + 8];
                    float h2 = Hs[(kb + tig + 4) * 132 + r];
                    float h3 = Hs[(kb + tig + 4) * 132 + r + 8];
                    uint32_t ah[4], al[4];
                    ah[0] = tf32_rna(h0); al[0] = tf32_rna(h0 - __uint_as_float(ah[0]));
                    ah[1] = tf32_rna(h1); al[1] = tf32_rna(h1 - __uint_as_float(ah[1]));
                    ah[2] = tf32_rna(h2); al[2] = tf32_rna(h2 - __uint_as_float(ah[2]));
                    ah[3] = tf32_rna(h3); al[3] = tf32_rna(h3 - __uint_as_float(ah[3]));
#pragma unroll
                    for (int j = 0; j < 6; j++) {
                        mma_tf32(acc[mi][j], ah, bh[j]);
                        mma_tf32(acc[mi][j], al, bh[j]);
                        mma_tf32(acc[mi][j], ah, bl[j]);
                    }
                }
            }
            // store partials
#pragma unroll
            for (int mi = 0; mi < 2; mi++) {
                int r = wm + mi * 16 + gid;
#pragma unroll
                for (int j = 0; j < 6; j++) {
                    int col = c0 + wn + j * 8 + tig * 2;
                    float* p0 = part + (((size_t)ks * 2 + d) * B + r) * G3 + col;
                    float* p1 = part + (((size_t)ks * 2 + d) * B + r + 8) * G3 + col;
                    *(float2*)p0 = make_float2(acc[mi][j][0], acc[mi][j][1]);
                    *(float2*)p1 = make_float2(acc[mi][j][2], acc[mi][j][3]);
                }
            }
        }
        grid_sync(bar, NCTA, &gen);

        // phase2: gates + masked update
        for (int it = cta * 256 + tid; it < total; it += nth) {
            int j  = it % H;
            int rr = (it / H) % B;
            int dd = it / (H * B);
            int te = (dd == 0) ? t : (T - 1 - t);
            int bo = perm[rr];
            int valid = te < lenp[rr];
            float hold = hcur[((size_t)dd * B + rr) * H + j];
            float hnew = hold;
            if (valid) {
                float hpr = 0.f, hpz = 0.f, hpn = 0.f;
#pragma unroll
                for (int s = 0; s < KS; s++) {
                    const float* pb = part + (((size_t)s * 2 + dd) * B + rr) * G3;
                    hpr += pb[j]; hpz += pb[H + j]; hpn += pb[2 * H + j];
                }
                const float* bb = b_hh + (size_t)dd * G3;
                hpr += bb[j]; hpz += bb[H + j]; hpn += bb[2 * H + j];
                const float* xr = xp + ((size_t)bo * T + te) * (2 * G3) + (size_t)dd * G3;
                float rg = 1.f / (1.f + expf(-(xr[j] + hpr)));
                float zg = 1.f / (1.f + expf(-(xr[H + j] + hpz)));
                float ng = tanhf(xr[2 * H + j] + rg * hpn);
                hnew = (1.f - zg) * ng + zg * hold;
            }
            hnxt[((size_t)dd * B + rr) * H + j] = hnew;
            out[((size_t)bo * T + te) * (2 * H) + dd * H + j] = valid ? hnew : 0.f;
        }
        grid_sync(bar, NCTA, &gen);
        float* tmp = hcur; hcur = hnxt; hnxt = tmp;
    }
}

// ---------------- segment means ----------------
__global__ __launch_bounds__(256) void seg_mean_kernel(
    const float* __restrict__ vf, const float* __restrict__ loc,
    const int* __restrict__ v_len,
    float* __restrict__ lmean, float* __restrict__ rmean, float* __restrict__ cat)
{
    const int b = blockIdx.x;
    const int col = blockIdx.y * 256 + threadIdx.x;
    const int vl = v_len[b];
    const float scale = (float)(vl - 1);
    const float l0 = loc[b * 2], l1 = loc[b * 2 + 1];
    const int cond = (l0 <= l1);
    const float lhi = cond ? l0 : 0.f;
    const float rlo = cond ? l1 : 1.f;
    const int lend   = (int)floorf(lhi * scale);
    const int rstart = (int)floorf(rlo * scale);
    const int rend   = vl - 1;
    const int ok_l = (0 <= lend);
    const int ok_r = (rstart <= rend);

    float ls = 0.f, rs = 0.f, gs = 0.f;
    for (int t = 0; t < TV; t++) {
        float v = vf[((size_t)b * TV + t) * 1024 + col];
        if (t < vl) gs += v;
        if (ok_l && t <= lend) ls += v;
        if (ok_r && t >= rstart && t <= rend) rs += v;
    }
    float lcnt = ok_l ? (float)(lend + 1) : 1.f;
    float rcnt = ok_r ? (float)(rend - rstart + 1) : 1.f;
    if (lcnt < 1.f) lcnt = 1.f;
    if (rcnt < 1.f) rcnt = 1.f;
    lmean[b * 1024 + col] = ls / lcnt;
    rmean[b * 1024 + col] = rs / rcnt;
    cat[(size_t)b * NCAT + 512 + col] = gs / (float)vl;
}

// ---------------- gather sen_fea ----------------
__global__ void gather_senfea(const float* __restrict__ words,
                              const int* __restrict__ lens,
                              float* __restrict__ out_sf, float* __restrict__ cat)
{
    const int b = blockIdx.x;
    const int t = lens[b] - 1;
    for (int c = threadIdx.x; c < 2 * SHID; c += blockDim.x) {
        float v = words[((size_t)b * TS + t) * (2 * SHID) + c];
        out_sf[(size_t)b * (2 * SHID) + c] = v;
        cat[(size_t)b * NCAT + c] = v;
    }
}

// ---------------- small GEMM with epilogue ----------------
__global__ __launch_bounds__(256) void gemm_small(
    const float* __restrict__ A, const float* __restrict__ W,
    const float* __restrict__ bias, const float* __restrict__ mul, int mulLd,
    float* __restrict__ C, int ldC, int M, int N, int K, int relu)
{
    const int n0 = blockIdx.x * 32, m0 = blockIdx.y * 32;
    __shared__ __align__(16) float As[32][34];
    __shared__ __align__(16) float Wsm[32][34];
    const int tid = threadIdx.x, ty = tid / 16, tx = tid % 16;
    float acc[2][2] = {{0.f, 0.f}, {0.f, 0.f}};

    for (int k0 = 0; k0 < K; k0 += 32) {
        for (int e = tid; e < 1024; e += 256) {
            int r = e / 32, k = e % 32;
            int kg = k0 + k;
            As[k][r]  = (kg < K) ? A[(size_t)(m0 + r) * K + kg] : 0.f;
            Wsm[k][r] = (kg < K) ? W[(size_t)(n0 + r) * K + kg] : 0.f;
        }
        __syncthreads();
#pragma unroll
        for (int k = 0; k < 32; k++) {
            float2 av = *(const float2*)&As[k][ty * 2];
            float2 wv = *(const float2*)&Wsm[k][tx * 2];
            acc[0][0] += av.x * wv.x;  acc[0][1] += av.x * wv.y;
            acc[1][0] += av.y * wv.x;  acc[1][1] += av.y * wv.y;
        }
        __syncthreads();
    }
#pragma unroll
    for (int i = 0; i < 2; i++) {
        int m = m0 + ty * 2 + i;
#pragma unroll
        for (int j = 0; j < 2; j++) {
            int n = n0 + tx * 2 + j;
            float v = acc[i][j] + bias[n];
            if (mul) v *= mul[(size_t)m * mulLd + n];
            if (relu) v = fmaxf(v, 0.f);
            C[(size_t)m * ldC + n] = v;
        }
    }
}

// ---------------- launch ----------------
extern "C" void kernel_launch(void* const* d_in, const int* in_sizes, int n_in,
                              void* d_out, int out_size)
{
    const float* gv     = (const float*)d_in[1];
    const float* sen    = (const float*)d_in[2];
    const float* loc    = (const float*)d_in[5];
    const int*   lens   = (const int*)  d_in[6];
    const int*   v_len  = (const int*)  d_in[7];
    const float* v_w_ih = (const float*)d_in[8];
    const float* v_w_hh = (const float*)d_in[9];
    const float* v_b_ih = (const float*)d_in[10];
    const float* v_b_hh = (const float*)d_in[11];
    const float* s_w_ih = (const float*)d_in[12];
    const float* s_w_hh = (const float*)d_in[13];
    const float* s_b_ih = (const float*)d_in[14];
    const float* s_b_hh = (const float*)d_in[15];
    const float* fc1_w  = (const float*)d_in[16];
    const float* fc1_b  = (const float*)d_in[17];
    const float* fc2_w  = (const float*)d_in[18];
    const float* fc2_b  = (const float*)d_in[19];
    const float* fc3_w  = (const float*)d_in[20];
    const float* fc3_b  = (const float*)d_in[21];
    const float* fc4_w  = (const float*)d_in[22];
    const float* fc4_b  = (const float*)d_in[23];

    float* out    = (float*)d_out;
    float* out_vf = out;
    float* out_sf = out + VF_ELEMS;
    float* out_ft = out + VF_ELEMS + SF_ELEMS;

    float *xp_v, *xp_s, *h_v, *h_s, *part_v, *part_s, *words;
    float *lmean, *rmean, *cat, *sproj;
    int *perm_v, *lenp_v, *perm_s, *lenp_s;
    unsigned* bar;
    cudaGetSymbolAddress((void**)&xp_v,   g_xp_v);
    cudaGetSymbolAddress((void**)&xp_s,   g_xp_s);
    cudaGetSymbolAddress((void**)&h_v,    g_h_v);
    cudaGetSymbolAddress((void**)&h_s,    g_h_s);
    cudaGetSymbolAddress((void**)&part_v, g_part_v);
    cudaGetSymbolAddress((void**)&part_s, g_part_s);
    cudaGetSymbolAddress((void**)&words,  g_words);
    cudaGetSymbolAddress((void**)&lmean,  g_lmean);
    cudaGetSymbolAddress((void**)&rmean,  g_rmean);
    cudaGetSymbolAddress((void**)&cat,    g_cat);
    cudaGetSymbolAddress((void**)&sproj,  g_sproj);
    cudaGetSymbolAddress((void**)&perm_v, g_perm_v);
    cudaGetSymbolAddress((void**)&lenp_v, g_lenp_v);
    cudaGetSymbolAddress((void**)&perm_s, g_perm_s);
    cudaGetSymbolAddress((void**)&lenp_s, g_lenp_s);
    cudaGetSymbolAddress((void**)&bar,    g_bar);

    // smem: Wh+Wl (2*64*98 u32) + Hs (64*132 f32) = 83,968 B
    const int SMEM = (2 * 64 * 98 + 64 * 132) * 4;
    cudaFuncSetAttribute(gru_persistent<512, 1536, 256, 16, 8>,
                         cudaFuncAttributeMaxDynamicSharedMemorySize, SMEM);
    cudaFuncSetAttribute(gru_persistent<256, 768, 40, 8, 4>,
                         cudaFuncAttributeMaxDynamicSharedMemorySize, SMEM);

    // 1. sort + zero
    sort_init_kernel<<<1, 128>>>(v_len, lens, perm_v, lenp_v, perm_s, lenp_s, bar);
    zero_h_kernel<<<(2*2*B*VHID + 255) / 256, 256>>>(h_v, h_s);

    // 2. input projections (3xTF32 tensor cores)
    gemm_tf32<<<dim3(3072/128, (B*TV)/128), 256>>>(gv,  v_w_ih, v_b_ih, xp_v,
                                                   B*TV, 3072, VIN, v_len, TV);
    gemm_tf32<<<dim3(1536/128, (B*TS)/128), 256>>>(sen, s_w_ih, s_b_ih, xp_s,
                                                   B*TS, 1536, SIN, lens, TS);

    // 3. persistent visual GRU (256 CTAs, tensor-core phase1)
    gru_persistent<512, 1536, 256, 16, 8><<<256, 256, SMEM>>>(
        xp_v, v_w_hh, v_b_hh, h_v, part_v, out_vf, perm_v, lenp_v, bar);

    // 4. persistent sentence GRU (64 CTAs)
    gru_persistent<256, 768, 40, 8, 4><<<64, 256, SMEM>>>(
        xp_s, s_w_hh, s_b_hh, h_s, part_s, words, perm_s, lenp_s, bar + 2);

    // 5. sen_fea gather
    gather_senfea<<<B, 256>>>(words, lens, out_sf, cat);

    // 6. segment means + global mean
    seg_mean_kernel<<<dim3(B, 4), 256>>>(out_vf, loc, v_len, lmean, rmean, cat);

    // 7. FC stack
    gemm_small<<<dim3(LCROSS/32, B/32), 256>>>(out_sf, fc2_w, fc2_b, nullptr, 0,
                                               sproj, LCROSS, B, LCROSS, 2*SHID, 0);
    gemm_small<<<dim3(LCROSS/32, B/32), 256>>>(lmean, fc1_w, fc1_b, sproj, LCROSS,
                                               cat + 1536, NCAT, B, LCROSS, 2*VHID, 1);
    gemm_small<<<dim3(LCROSS/32, B/32), 256>>>(rmean, fc1_w, fc1_b, sproj, LCROSS,
                                               cat + 2048, NCAT, B, LCROSS, 2*VHID, 1);
    gemm_small<<<dim3(NLOC/32, B/32), 256>>>(loc, fc3_w, fc3_b, nullptr, 0,
                                             cat + 2560, NCAT, B, NLOC, 2, 1);
    gemm_small<<<dim3(NFEAT/32, B/32), 256>>>(cat, fc4_w, fc4_b, nullptr, 0,
                                              out_ft, NFEAT, B, NFEAT, NCAT, 1);
}

// round 6
// speedup vs baseline: 2.2648x; 1.2869x over previous
#include <cuda_runtime.h>
#include <math.h>
#include <stdint.h>

// ---------------- problem constants ----------------
#define B        128
#define TV       256
#define TS       40
#define VIN      1024
#define VHID     512
#define SIN      300
#define SHID     256
#define NCAT     2624
#define NFEAT    1024
#define LCROSS   512
#define NLOC     64

#define VF_ELEMS   ((size_t)B*TV*2*VHID)
#define SF_ELEMS   ((size_t)B*2*SHID)

// ---------------- scratch (__device__ globals) ----------------
__device__ float g_xp_v[(size_t)B*TV*3072];
__device__ float g_xp_s[(size_t)B*TS*1536];
__device__ float g_h_v[2*2*B*VHID];
__device__ float g_h_s[2*2*B*SHID];
__device__ float g_part_v[8*2*B*1536];
__device__ float g_part_s[4*2*B*768];
__device__ float g_words[(size_t)B*TS*2*SHID];
__device__ float g_lmean[B*1024];
__device__ float g_rmean[B*1024];
__device__ float g_cat[B*NCAT];
__device__ float g_sproj[B*LCROSS];
__device__ int   g_perm_v[B], g_lenp_v[B];
__device__ int   g_perm_s[B], g_lenp_s[B];
__device__ unsigned g_bar[4];

// ---------------- init ----------------
__global__ void sort_init_kernel(const int* __restrict__ v_len,
                                 const int* __restrict__ lens,
                                 int* pv, int* lv, int* ps, int* ls,
                                 unsigned* bar)
{
    int i = threadIdx.x;
    if (i < 4) bar[i] = 0u;
    int a = v_len[i], rank = 0;
    for (int j = 0; j < B; j++) {
        int c = v_len[j];
        rank += (c > a) || (c == a && j < i);
    }
    pv[rank] = i; lv[rank] = a;
    a = lens[i]; rank = 0;
    for (int j = 0; j < B; j++) {
        int c = lens[j];
        rank += (c > a) || (c == a && j < i);
    }
    ps[rank] = i; ls[rank] = a;
}

__global__ void zero_h_kernel(float* hv, float* hs) {
    int i = blockIdx.x * blockDim.x + threadIdx.x;
    if (i < 2*2*B*VHID) hv[i] = 0.f;
    if (i < 2*2*B*SHID) hs[i] = 0.f;
}

// ---------------- tf32 / cp.async helpers ----------------
__device__ __forceinline__ uint32_t tf32_rna(float x) {
    uint32_t r;
    asm("cvt.rna.tf32.f32 %0, %1;" : "=r"(r) : "f"(x));
    return r;
}
__device__ __forceinline__ void mma_tf32(float* d, const uint32_t* a, const uint32_t* b) {
    asm volatile(
        "mma.sync.aligned.m16n8k8.row.col.f32.tf32.tf32.f32 "
        "{%0,%1,%2,%3}, {%4,%5,%6,%7}, {%8,%9}, {%0,%1,%2,%3};"
        : "+f"(d[0]), "+f"(d[1]), "+f"(d[2]), "+f"(d[3])
        : "r"(a[0]), "r"(a[1]), "r"(a[2]), "r"(a[3]), "r"(b[0]), "r"(b[1]));
}
__device__ __forceinline__ void cp_async16(uint32_t saddr, const void* g, int src_bytes) {
    asm volatile("cp.async.cg.shared.global [%0], [%1], 16, %2;"
                 :: "r"(saddr), "l"(g), "r"(src_bytes));
}
__device__ __forceinline__ void cp_commit() {
    asm volatile("cp.async.commit_group;");
}
template<int N>
__device__ __forceinline__ void cp_wait() {
    asm volatile("cp.async.wait_group %0;" :: "n"(N));
}

// ---------------- pipelined tensor-core GEMM: C = A @ W^T + bias ----------
// 128x128 tile, BK=16, double-buffered cp.async staging of raw fp32 tiles,
// tf32 hi/lo split done per-fragment in registers (3xTF32 compensation).
// __launch_bounds__(256,2): 2 CTAs/SM so staging and tensor work overlap.
__global__ __launch_bounds__(256, 2) void gemm_tf32(
    const float* __restrict__ A, const float* __restrict__ W,
    const float* __restrict__ bias, float* __restrict__ C,
    int M, int N, int K, const int* __restrict__ lens, int T)
{
    const int n0 = blockIdx.x * 128;
    const int m0 = blockIdx.y * 128;
    const int tid = threadIdx.x;

    __shared__ __align__(16) float As[2][128][20];
    __shared__ __align__(16) float Ws[2][128][20];
    __shared__ int s_any;

    if (lens) {
        if (tid == 0) {
            int any = 0;
            for (int r = 0; r < 128; r++) {
                int row = m0 + r;
                if (row % T < lens[row / T]) { any = 1; break; }
            }
            s_any = any;
        }
        __syncthreads();
        if (!s_any) return;
    }

    const int wid  = tid / 32, lane = tid % 32;
    const int wm   = (wid / 4) * 64;
    const int wn   = (wid % 4) * 32;
    const int gid  = lane >> 2, tig = lane & 3;
    const int niter = (K + 15) >> 4;

    float acc[4][4][4];
#pragma unroll
    for (int i = 0; i < 4; i++)
#pragma unroll
        for (int j = 0; j < 4; j++)
#pragma unroll
            for (int c = 0; c < 4; c++) acc[i][j][c] = 0.f;

    // staging: 512 16B-chunks per matrix (128 rows x 4 chunks), 2 per thread
#define STAGE(bf, k0)                                                          \
    do {                                                                       \
        _Pragma("unroll")                                                      \
        for (int i_ = 0; i_ < 2; i_++) {                                       \
            int c_   = tid + 256 * i_;                                         \
            int row_ = c_ >> 2, kc_ = (c_ & 3) * 4;                            \
            int kg_  = (k0) + kc_;                                             \
            int by_  = (K - kg_) * 4;                                          \
            by_ = by_ < 0 ? 0 : (by_ > 16 ? 16 : by_);                         \
            cp_async16((uint32_t)__cvta_generic_to_shared(&As[bf][row_][kc_]), \
                       A + (size_t)(m0 + row_) * K + kg_, by_);                \
            cp_async16((uint32_t)__cvta_generic_to_shared(&Ws[bf][row_][kc_]), \
                       W + (size_t)(n0 + row_) * K + kg_, by_);                \
        }                                                                      \
    } while (0)

    STAGE(0, 0);
    cp_commit();

    for (int kt = 0; kt < niter; kt++) {
        const int buf = kt & 1;
        if (kt + 1 < niter) {
            STAGE(buf ^ 1, (kt + 1) * 16);
            cp_commit();
            cp_wait<1>();
        } else {
            cp_wait<0>();
        }
        __syncthreads();

#pragma unroll
        for (int ks = 0; ks < 2; ks++) {
            const int kb = ks * 8;
            uint32_t bh[4][2], bl[4][2];
#pragma unroll
            for (int j = 0; j < 4; j++) {
                int nc = wn + j * 8 + gid;
                float w0 = Ws[buf][nc][kb + tig];
                float w1 = Ws[buf][nc][kb + tig + 4];
                bh[j][0] = tf32_rna(w0); bl[j][0] = tf32_rna(w0 - __uint_as_float(bh[j][0]));
                bh[j][1] = tf32_rna(w1); bl[j][1] = tf32_rna(w1 - __uint_as_float(bh[j][1]));
            }
#pragma unroll
            for (int mi = 0; mi < 4; mi++) {
                int mr = wm + mi * 16 + gid;
                float a0 = As[buf][mr][kb + tig];
                float a1 = As[buf][mr + 8][kb + tig];
                float a2 = As[buf][mr][kb + tig + 4];
                float a3 = As[buf][mr + 8][kb + tig + 4];
                uint32_t ah[4], al[4];
                ah[0] = tf32_rna(a0); al[0] = tf32_rna(a0 - __uint_as_float(ah[0]));
                ah[1] = tf32_rna(a1); al[1] = tf32_rna(a1 - __uint_as_float(ah[1]));
                ah[2] = tf32_rna(a2); al[2] = tf32_rna(a2 - __uint_as_float(ah[2]));
                ah[3] = tf32_rna(a3); al[3] = tf32_rna(a3 - __uint_as_float(ah[3]));
#pragma unroll
                for (int j = 0; j < 4; j++) {
                    mma_tf32(acc[mi][j], ah, bh[j]);
                    mma_tf32(acc[mi][j], al, bh[j]);
                    mma_tf32(acc[mi][j], ah, bl[j]);
                }
            }
        }
        __syncthreads();
    }
#undef STAGE

#pragma unroll
    for (int i = 0; i < 4; i++) {
#pragma unroll
        for (int j = 0; j < 4; j++) {
            int col = n0 + wn + j * 8 + tig * 2;
            float b0 = bias[col], b1 = bias[col + 1];
            int r0g = m0 + wm + i * 16 + gid;
            *(float2*)&C[(size_t)r0g * N + col] =
                make_float2(acc[i][j][0] + b0, acc[i][j][1] + b1);
            *(float2*)&C[(size_t)(r0g + 8) * N + col] =
                make_float2(acc[i][j][2] + b0, acc[i][j][3] + b1);
        }
    }
}

// ---------------- software grid barrier (volatile-load poll) ----------------
__device__ __forceinline__ void grid_sync(unsigned* bar, int ncta, unsigned* gen)
{
    __syncthreads();
    if (threadIdx.x == 0) {
        unsigned target = *gen + 1u;
        __threadfence();
        unsigned arr = atomicAdd(&bar[0], 1u);
        if (arr == (unsigned)(ncta - 1)) {
            atomicExch(&bar[0], 0u);
            __threadfence();
            atomicExch(&bar[1], target);
        } else {
            while (*(volatile unsigned*)&bar[1] < target) { }
        }
        __threadfence();
        *gen = target;
    }
    __syncthreads();
}

// ---------------- persistent weight-stationary GRU, tensor-core phase1 ------
template<int H, int G3, int T, int NCT, int KS>
__global__ __launch_bounds__(256, 2) void gru_persistent(
    const float* __restrict__ xp, const float* __restrict__ w_hh,
    const float* __restrict__ b_hh, float* __restrict__ hbuf,
    float* __restrict__ part, float* __restrict__ out,
    const int* __restrict__ perm, const int* __restrict__ lenp,
    unsigned* __restrict__ bar)
{
    constexpr int KC = 64;
    constexpr int NCTA = 2 * NCT * KS;
    extern __shared__ float sm[];
    uint32_t* Wh = (uint32_t*)sm;             // [KC][98]
    uint32_t* Wl = Wh + KC * 98;              // [KC][98]
    float*    Hs = (float*)(Wl + KC * 98);    // [KC][132]

    const int cta = blockIdx.x;
    const int d   = cta / (NCT * KS);
    const int ct  = (cta % (NCT * KS)) / KS;
    const int ks  = cta % KS;
    const int c0  = ct * 96;
    const int k0  = ks * KC;
    const int tid = threadIdx.x;
    const int wid = tid / 32, lane = tid % 32;
    const int gid = lane >> 2, tig = lane & 3;
    const int wm  = (wid >> 1) * 32;
    const int wn  = (wid & 1) * 48;

    for (int e = tid; e < KC * 96; e += 256) {
        int k = e % KC, c = e / KC;
        float w = w_hh[((size_t)d * G3 + c0 + c) * H + k0 + k];
        uint32_t wh = tf32_rna(w);
        Wh[k * 98 + c] = wh;
        Wl[k * 98 + c] = tf32_rna(w - __uint_as_float(wh));
    }

    const int myLen = lenp[wm];
    unsigned gen = 0;
    float* hcur = hbuf;
    float* hnxt = hbuf + 2 * B * H;
    const int total = 2 * B * H;
    const int nth   = NCTA * 256;

    for (int t = 0; t < T; t++) {
        const int te1 = (d == 0) ? t : (T - 1 - t);

        for (int e = tid; e < KC * B; e += 256) {
            int k = e % KC, r = e / KC;
            Hs[k * 132 + r] = hcur[((size_t)d * B + r) * H + k0 + k];
        }
        __syncthreads();

        if (te1 < myLen) {
            float acc[2][6][4];
#pragma unroll
            for (int i = 0; i < 2; i++)
#pragma unroll
                for (int j = 0; j < 6; j++)
#pragma unroll
                    for (int c = 0; c < 4; c++) acc[i][j][c] = 0.f;

#pragma unroll
            for (int k8 = 0; k8 < KC / 8; k8++) {
                const int kb = k8 * 8;
                uint32_t bh[6][2], bl[6][2];
#pragma unroll
                for (int j = 0; j < 6; j++) {
                    int c = wn + j * 8 + gid;
                    bh[j][0] = Wh[(kb + tig) * 98 + c];
                    bh[j][1] = Wh[(kb + tig + 4) * 98 + c];
                    bl[j][0] = Wl[(kb + tig) * 98 + c];
                    bl[j][1] = Wl[(kb + tig + 4) * 98 + c];
                }
#pragma unroll
                for (int mi = 0; mi < 2; mi++) {
                    int r = wm + mi * 16 + gid;
                    float h0 = Hs[(kb + tig) * 132 + r];
                    float h1 = Hs[(kb + tig) * 132 + r + 8];
                    float h2 = Hs[(kb + tig + 4) * 132 + r];
                    float h3 = Hs[(kb + tig + 4) * 132 + r + 8];
                    uint32_t ah[4], al[4];
                    ah[0] = tf32_rna(h0); al[0] = tf32_rna(h0 - __uint_as_float(ah[0]));
                    ah[1] = tf32_rna(h1); al[1] = tf32_rna(h1 - __uint_as_float(ah[1]));
                    ah[2] = tf32_rna(h2); al[2] = tf32_rna(h2 - __uint_as_float(ah[2]));
                    ah[3] = tf32_rna(h3); al[3] = tf32_rna(h3 - __uint_as_float(ah[3]));
#pragma unroll
                    for (int j = 0; j < 6; j++) {
                        mma_tf32(acc[mi][j], ah, bh[j]);
                        mma_tf32(acc[mi][j], al, bh[j]);
                        mma_tf32(acc[mi][j], ah, bl[j]);
                    }
                }
            }
#pragma unroll
            for (int mi = 0; mi < 2; mi++) {
                int r = wm + mi * 16 + gid;
#pragma unroll
                for (int j = 0; j < 6; j++) {
                    int col = c0 + wn + j * 8 + tig * 2;
                    float* p0 = part + (((size_t)ks * 2 + d) * B + r) * G3 + col;
                    float* p1 = part + (((size_t)ks * 2 + d) * B + r + 8) * G3 + col;
                    *(float2*)p0 = make_float2(acc[mi][j][0], acc[mi][j][1]);
                    *(float2*)p1 = make_float2(acc[mi][j][2], acc[mi][j][3]);
                }
            }
        }
        grid_sync(bar, NCTA, &gen);

        for (int it = cta * 256 + tid; it < total; it += nth) {
            int j  = it % H;
            int rr = (it / H) % B;
            int dd = it / (H * B);
            int te = (dd == 0) ? t : (T - 1 - t);
            int bo = perm[rr];
            int valid = te < lenp[rr];
            float hold = hcur[((size_t)dd * B + rr) * H + j];
            float hnew = hold;
            if (valid) {
                float hpr = 0.f, hpz = 0.f, hpn = 0.f;
#pragma unroll
                for (int s = 0; s < KS; s++) {
                    const float* pb = part + (((size_t)s * 2 + dd) * B + rr) * G3;
                    hpr += pb[j]; hpz += pb[H + j]; hpn += pb[2 * H + j];
                }
                const float* bb = b_hh + (size_t)dd * G3;
                hpr += bb[j]; hpz += bb[H + j]; hpn += bb[2 * H + j];
                const float* xr = xp + ((size_t)bo * T + te) * (2 * G3) + (size_t)dd * G3;
                float rg = 1.f / (1.f + expf(-(xr[j] + hpr)));
                float zg = 1.f / (1.f + expf(-(xr[H + j] + hpz)));
                float ng = tanhf(xr[2 * H + j] + rg * hpn);
                hnew = (1.f - zg) * ng + zg * hold;
            }
            hnxt[((size_t)dd * B + rr) * H + j] = hnew;
            out[((size_t)bo * T + te) * (2 * H) + dd * H + j] = valid ? hnew : 0.f;
        }
        grid_sync(bar, NCTA, &gen);
        float* tmp = hcur; hcur = hnxt; hnxt = tmp;
    }
}

// ---------------- segment means ----------------
__global__ __launch_bounds__(256) void seg_mean_kernel(
    const float* __restrict__ vf, const float* __restrict__ loc,
    const int* __restrict__ v_len,
    float* __restrict__ lmean, float* __restrict__ rmean, float* __restrict__ cat)
{
    const int b = blockIdx.x;
    const int col = blockIdx.y * 256 + threadIdx.x;
    const int vl = v_len[b];
    const float scale = (float)(vl - 1);
    const float l0 = loc[b * 2], l1 = loc[b * 2 + 1];
    const int cond = (l0 <= l1);
    const float lhi = cond ? l0 : 0.f;
    const float rlo = cond ? l1 : 1.f;
    const int lend   = (int)floorf(lhi * scale);
    const int rstart = (int)floorf(rlo * scale);
    const int rend   = vl - 1;
    const int ok_l = (0 <= lend);
    const int ok_r = (rstart <= rend);

    float ls = 0.f, rs = 0.f, gs = 0.f;
    for (int t = 0; t < TV; t++) {
        float v = vf[((size_t)b * TV + t) * 1024 + col];
        if (t < vl) gs += v;
        if (ok_l && t <= lend) ls += v;
        if (ok_r && t >= rstart && t <= rend) rs += v;
    }
    float lcnt = ok_l ? (float)(lend + 1) : 1.f;
    float rcnt = ok_r ? (float)(rend - rstart + 1) : 1.f;
    if (lcnt < 1.f) lcnt = 1.f;
    if (rcnt < 1.f) rcnt = 1.f;
    lmean[b * 1024 + col] = ls / lcnt;
    rmean[b * 1024 + col] = rs / rcnt;
    cat[(size_t)b * NCAT + 512 + col] = gs / (float)vl;
}

// ---------------- gather sen_fea ----------------
__global__ void gather_senfea(const float* __restrict__ words,
                              const int* __restrict__ lens,
                              float* __restrict__ out_sf, float* __restrict__ cat)
{
    const int b = blockIdx.x;
    const int t = lens[b] - 1;
    for (int c = threadIdx.x; c < 2 * SHID; c += blockDim.x) {
        float v = words[((size_t)b * TS + t) * (2 * SHID) + c];
        out_sf[(size_t)b * (2 * SHID) + c] = v;
        cat[(size_t)b * NCAT + c] = v;
    }
}

// ---------------- small GEMM with epilogue ----------------
__global__ __launch_bounds__(256) void gemm_small(
    const float* __restrict__ A, const float* __restrict__ W,
    const float* __restrict__ bias, const float* __restrict__ mul, int mulLd,
    float* __restrict__ C, int ldC, int M, int N, int K, int relu)
{
    const int n0 = blockIdx.x * 32, m0 = blockIdx.y * 32;
    __shared__ __align__(16) float As[32][34];
    __shared__ __align__(16) float Wsm[32][34];
    const int tid = threadIdx.x, ty = tid / 16, tx = tid % 16;
    float acc[2][2] = {{0.f, 0.f}, {0.f, 0.f}};

    for (int k0 = 0; k0 < K; k0 += 32) {
        for (int e = tid; e < 1024; e += 256) {
            int r = e / 32, k = e % 32;
            int kg = k0 + k;
            As[k][r]  = (kg < K) ? A[(size_t)(m0 + r) * K + kg] : 0.f;
            Wsm[k][r] = (kg < K) ? W[(size_t)(n0 + r) * K + kg] : 0.f;
        }
        __syncthreads();
#pragma unroll
        for (int k = 0; k < 32; k++) {
            float2 av = *(const float2*)&As[k][ty * 2];
            float2 wv = *(const float2*)&Wsm[k][tx * 2];
            acc[0][0] += av.x * wv.x;  acc[0][1] += av.x * wv.y;
            acc[1][0] += av.y * wv.x;  acc[1][1] += av.y * wv.y;
        }
        __syncthreads();
    }
#pragma unroll
    for (int i = 0; i < 2; i++) {
        int m = m0 + ty * 2 + i;
#pragma unroll
        for (int j = 0; j < 2; j++) {
            int n = n0 + tx * 2 + j;
            float v = acc[i][j] + bias[n];
            if (mul) v *= mul[(size_t)m * mulLd + n];
            if (relu) v = fmaxf(v, 0.f);
            C[(size_t)m * ldC + n] = v;
        }
    }
}

// ---------------- launch ----------------
extern "C" void kernel_launch(void* const* d_in, const int* in_sizes, int n_in,
                              void* d_out, int out_size)
{
    const float* gv     = (const float*)d_in[1];
    const float* sen    = (const float*)d_in[2];
    const float* loc    = (const float*)d_in[5];
    const int*   lens   = (const int*)  d_in[6];
    const int*   v_len  = (const int*)  d_in[7];
    const float* v_w_ih = (const float*)d_in[8];
    const float* v_w_hh = (const float*)d_in[9];
    const float* v_b_ih = (const float*)d_in[10];
    const float* v_b_hh = (const float*)d_in[11];
    const float* s_w_ih = (const float*)d_in[12];
    const float* s_w_hh = (const float*)d_in[13];
    const float* s_b_ih = (const float*)d_in[14];
    const float* s_b_hh = (const float*)d_in[15];
    const float* fc1_w  = (const float*)d_in[16];
    const float* fc1_b  = (const float*)d_in[17];
    const float* fc2_w  = (const float*)d_in[18];
    const float* fc2_b  = (const float*)d_in[19];
    const float* fc3_w  = (const float*)d_in[20];
    const float* fc3_b  = (const float*)d_in[21];
    const float* fc4_w  = (const float*)d_in[22];
    const float* fc4_b  = (const float*)d_in[23];

    float* out    = (float*)d_out;
    float* out_vf = out;
    float* out_sf = out + VF_ELEMS;
    float* out_ft = out + VF_ELEMS + SF_ELEMS;

    float *xp_v, *xp_s, *h_v, *h_s, *part_v, *part_s, *words;
    float *lmean, *rmean, *cat, *sproj;
    int *perm_v, *lenp_v, *perm_s, *lenp_s;
    unsigned* bar;
    cudaGetSymbolAddress((void**)&xp_v,   g_xp_v);
    cudaGetSymbolAddress((void**)&xp_s,   g_xp_s);
    cudaGetSymbolAddress((void**)&h_v,    g_h_v);
    cudaGetSymbolAddress((void**)&h_s,    g_h_s);
    cudaGetSymbolAddress((void**)&part_v, g_part_v);
    cudaGetSymbolAddress((void**)&part_s, g_part_s);
    cudaGetSymbolAddress((void**)&words,  g_words);
    cudaGetSymbolAddress((void**)&lmean,  g_lmean);
    cudaGetSymbolAddress((void**)&rmean,  g_rmean);
    cudaGetSymbolAddress((void**)&cat,    g_cat);
    cudaGetSymbolAddress((void**)&sproj,  g_sproj);
    cudaGetSymbolAddress((void**)&perm_v, g_perm_v);
    cudaGetSymbolAddress((void**)&lenp_v, g_lenp_v);
    cudaGetSymbolAddress((void**)&perm_s, g_perm_s);
    cudaGetSymbolAddress((void**)&lenp_s, g_lenp_s);
    cudaGetSymbolAddress((void**)&bar,    g_bar);

    const int SMEM = (2 * 64 * 98 + 64 * 132) * 4;
    cudaFuncSetAttribute(gru_persistent<512, 1536, 256, 16, 8>,
                         cudaFuncAttributeMaxDynamicSharedMemorySize, SMEM);
    cudaFuncSetAttribute(gru_persistent<256, 768, 40, 8, 4>,
                         cudaFuncAttributeMaxDynamicSharedMemorySize, SMEM);

    // 1. sort + zero
    sort_init_kernel<<<1, 128>>>(v_len, lens, perm_v, lenp_v, perm_s, lenp_s, bar);
    zero_h_kernel<<<(2*2*B*VHID + 255) / 256, 256>>>(h_v, h_s);

    // 2. input projections (pipelined 3xTF32 tensor cores)
    gemm_tf32<<<dim3(3072/128, (B*TV)/128), 256>>>(gv,  v_w_ih, v_b_ih, xp_v,
                                                   B*TV, 3072, VIN, v_len, TV);
    gemm_tf32<<<dim3(1536/128, (B*TS)/128), 256>>>(sen, s_w_ih, s_b_ih, xp_s,
                                                   B*TS, 1536, SIN, lens, TS);

    // 3. persistent visual GRU (256 CTAs, tensor-core phase1)
    gru_persistent<512, 1536, 256, 16, 8><<<256, 256, SMEM>>>(
        xp_v, v_w_hh, v_b_hh, h_v, part_v, out_vf, perm_v, lenp_v, bar);

    // 4. persistent sentence GRU (64 CTAs)
    gru_persistent<256, 768, 40, 8, 4><<<64, 256, SMEM>>>(
        xp_s, s_w_hh, s_b_hh, h_s, part_s, words, perm_s, lenp_s, bar + 2);

    // 5. sen_fea gather
    gather_senfea<<<B, 256>>>(words, lens, out_sf, cat);

    // 6. segment means + global mean
    seg_mean_kernel<<<dim3(B, 4), 256>>>(out_vf, loc, v_len, lmean, rmean, cat);

    // 7. FC stack
    gemm_small<<<dim3(LCROSS/32, B/32), 256>>>(out_sf, fc2_w, fc2_b, nullptr, 0,
                                               sproj, LCROSS, B, LCROSS, 2*SHID, 0);
    gemm_small<<<dim3(LCROSS/32, B/32), 256>>>(lmean, fc1_w, fc1_b, sproj, LCROSS,
                                               cat + 1536, NCAT, B, LCROSS, 2*VHID, 1);
    gemm_small<<<dim3(LCROSS/32, B/32), 256>>>(rmean, fc1_w, fc1_b, sproj, LCROSS,
                                               cat + 2048, NCAT, B, LCROSS, 2*VHID, 1);
    gemm_small<<<dim3(NLOC/32, B/32), 256>>>(loc, fc3_w, fc3_b, nullptr, 0,
                                             cat + 2560, NCAT, B, NLOC, 2, 1);
    gemm_small<<<dim3(NFEAT/32, B/32), 256>>>(cat, fc4_w, fc4_b, nullptr, 0,
                                              out_ft, NFEAT, B, NFEAT, NCAT, 1);
}

// round 7
// speedup vs baseline: 2.4931x; 1.1008x over previous
#include <cuda_runtime.h>
#include <cuda_bf16.h>
#include <math.h>
#include <stdint.h>

// ---------------- problem constants ----------------
#define B        128
#define TV       256
#define TS       40
#define VIN      1024
#define VHID     512
#define SIN      300
#define SHID     256
#define NCAT     2624
#define NFEAT    1024
#define LCROSS   512
#define NLOC     64

#define VF_ELEMS   ((size_t)B*TV*2*VHID)
#define SF_ELEMS   ((size_t)B*2*SHID)

// ---------------- scratch (__device__ globals) ----------------
__device__ float g_xp_v[(size_t)B*TV*3072];
__device__ float g_xp_s[(size_t)B*TS*1536];
__device__ float g_h_v[2*2*B*VHID];
__device__ float g_h_s[2*2*B*SHID];
__device__ float g_part_v[8*2*B*1536];
__device__ float g_part_s[4*2*B*768];
__device__ float g_words[(size_t)B*TS*2*SHID];
__device__ float g_lmean[B*1024];
__device__ float g_rmean[B*1024];
__device__ float g_cat[B*NCAT];
__device__ float g_sproj[B*LCROSS];
__device__ int   g_perm_v[B], g_lenp_v[B];
__device__ int   g_perm_s[B], g_lenp_s[B];
__device__ unsigned g_bar[4];

// ---------------- init ----------------
__global__ void sort_init_kernel(const int* __restrict__ v_len,
                                 const int* __restrict__ lens,
                                 int* pv, int* lv, int* ps, int* ls,
                                 unsigned* bar)
{
    int i = threadIdx.x;
    if (i < 4) bar[i] = 0u;
    int a = v_len[i], rank = 0;
    for (int j = 0; j < B; j++) {
        int c = v_len[j];
        rank += (c > a) || (c == a && j < i);
    }
    pv[rank] = i; lv[rank] = a;
    a = lens[i]; rank = 0;
    for (int j = 0; j < B; j++) {
        int c = lens[j];
        rank += (c > a) || (c == a && j < i);
    }
    ps[rank] = i; ls[rank] = a;
}

__global__ void zero_h_kernel(float* hv, float* hs) {
    int i = blockIdx.x * blockDim.x + threadIdx.x;
    if (i < 2*2*B*VHID) hv[i] = 0.f;
    if (i < 2*2*B*SHID) hs[i] = 0.f;
}

// ---------------- numeric helpers ----------------
__device__ __forceinline__ uint32_t tf32_rna(float x) {
    uint32_t r;
    asm("cvt.rna.tf32.f32 %0, %1;" : "=r"(r) : "f"(x));
    return r;
}
__device__ __forceinline__ void mma_tf32(float* d, const uint32_t* a, const uint32_t* b) {
    asm volatile(
        "mma.sync.aligned.m16n8k8.row.col.f32.tf32.tf32.f32 "
        "{%0,%1,%2,%3}, {%4,%5,%6,%7}, {%8,%9}, {%0,%1,%2,%3};"
        : "+f"(d[0]), "+f"(d[1]), "+f"(d[2]), "+f"(d[3])
        : "r"(a[0]), "r"(a[1]), "r"(a[2]), "r"(a[3]), "r"(b[0]), "r"(b[1]));
}
__device__ __forceinline__ void mma_bf16(float* d, const uint32_t* a, const uint32_t* b) {
    asm volatile(
        "mma.sync.aligned.m16n8k16.row.col.f32.bf16.bf16.f32 "
        "{%0,%1,%2,%3}, {%4,%5,%6,%7}, {%8,%9}, {%0,%1,%2,%3};"
        : "+f"(d[0]), "+f"(d[1]), "+f"(d[2]), "+f"(d[3])
        : "r"(a[0]), "r"(a[1]), "r"(a[2]), "r"(a[3]), "r"(b[0]), "r"(b[1]));
}
// pack two bf16 (lo = element k, hi = element k+1)
__device__ __forceinline__ uint32_t bfpack(__nv_bfloat16 lo, __nv_bfloat16 hi) {
    uint32_t l = __bfloat16_as_ushort(lo);
    uint32_t h = __bfloat16_as_ushort(hi);
    return l | (h << 16);
}
// split float pair into bf16 hi-pack + residual lo-pack
__device__ __forceinline__ void bfsplit2(float x0, float x1,
                                         uint32_t& hi, uint32_t& lo) {
    __nv_bfloat16 h0 = __float2bfloat16_rn(x0);
    __nv_bfloat16 h1 = __float2bfloat16_rn(x1);
    hi = bfpack(h0, h1);
    __nv_bfloat16 l0 = __float2bfloat16_rn(x0 - __bfloat162float(h0));
    __nv_bfloat16 l1 = __float2bfloat16_rn(x1 - __bfloat162float(h1));
    lo = bfpack(l0, l1);
}
__device__ __forceinline__ float4 ld_guard4(const float* p, int kg, int K) {
    if (kg + 4 <= K) return *(const float4*)p;
    float4 v;
    v.x = (kg     < K) ? p[0] : 0.f;
    v.y = (kg + 1 < K) ? p[1] : 0.f;
    v.z = (kg + 2 < K) ? p[2] : 0.f;
    v.w = (kg + 3 < K) ? p[3] : 0.f;
    return v;
}

// ---------------- 3xBF16 tensor-core GEMM: C = A @ W^T + bias --------------
// 128x128 tile, BK=16 (one m16n8k16 k-step), 8 warps (2x4), warp tile 64x32.
// hi/lo bf16 split done ONCE per element at staging (packed bf16x2 in smem);
// compute path is pure LDS + HMMA. Reg-prefetch + 2 smem buffers, 1 sync/iter.
__global__ __launch_bounds__(256, 2) void gemm_bf16x3(
    const float* __restrict__ A, const float* __restrict__ W,
    const float* __restrict__ bias, float* __restrict__ C,
    int M, int N, int K, const int* __restrict__ lens, int T)
{
    const int n0 = blockIdx.x * 128;
    const int m0 = blockIdx.y * 128;
    const int tid = threadIdx.x;

    __shared__ uint32_t Ah[2][8][132], Al[2][8][132];
    __shared__ uint32_t Wh[2][8][132], Wl[2][8][132];
    __shared__ int s_any;

    if (lens) {
        if (tid == 0) {
            int any = 0;
            for (int r = 0; r < 128; r++) {
                int row = m0 + r;
                if (row % T < lens[row / T]) { any = 1; break; }
            }
            s_any = any;
        }
        __syncthreads();
        if (!s_any) return;
    }

    const int wid  = tid / 32, lane = tid % 32;
    const int wm   = (wid / 4) * 64;
    const int wn   = (wid % 4) * 32;
    const int gid  = lane >> 2, tig = lane & 3;
    const int niter = (K + 15) >> 4;

    // per-thread staging coords: 2 chunks of float4 per matrix per iter
    const int c0r = tid >> 2,          c0k = (tid & 3) * 4;         // chunk 0
    const int c1r = (tid + 256) >> 2,  c1k = ((tid + 256) & 3) * 4; // chunk 1

    float acc[4][4][4];
#pragma unroll
    for (int i = 0; i < 4; i++)
#pragma unroll
        for (int j = 0; j < 4; j++)
#pragma unroll
            for (int c = 0; c < 4; c++) acc[i][j][c] = 0.f;

    float4 ra0, ra1, rw0, rw1;
    // prefetch iter 0
    ra0 = ld_guard4(A + (size_t)(m0 + c0r) * K + c0k, c0k, K);
    ra1 = ld_guard4(A + (size_t)(m0 + c1r) * K + c1k, c1k, K);
    rw0 = ld_guard4(W + (size_t)(n0 + c0r) * K + c0k, c0k, K);
    rw1 = ld_guard4(W + (size_t)(n0 + c1r) * K + c1k, c1k, K);

    for (int kt = 0; kt < niter; kt++) {
        const int buf = kt & 1;

        // convert + store packed hi/lo (k2 index = k/2 within slab)
        {
            uint32_t h, l;
            int k2 = c0k >> 1;
            bfsplit2(ra0.x, ra0.y, h, l); Ah[buf][k2][c0r] = h;     Al[buf][k2][c0r] = l;
            bfsplit2(ra0.z, ra0.w, h, l); Ah[buf][k2 + 1][c0r] = h; Al[buf][k2 + 1][c0r] = l;
            bfsplit2(rw0.x, rw0.y, h, l); Wh[buf][k2][c0r] = h;     Wl[buf][k2][c0r] = l;
            bfsplit2(rw0.z, rw0.w, h, l); Wh[buf][k2 + 1][c0r] = h; Wl[buf][k2 + 1][c0r] = l;
            k2 = c1k >> 1;
            bfsplit2(ra1.x, ra1.y, h, l); Ah[buf][k2][c1r] = h;     Al[buf][k2][c1r] = l;
            bfsplit2(ra1.z, ra1.w, h, l); Ah[buf][k2 + 1][c1r] = h; Al[buf][k2 + 1][c1r] = l;
            bfsplit2(rw1.x, rw1.y, h, l); Wh[buf][k2][c1r] = h;     Wl[buf][k2][c1r] = l;
            bfsplit2(rw1.z, rw1.w, h, l); Wh[buf][k2 + 1][c1r] = h; Wl[buf][k2 + 1][c1r] = l;
        }
        __syncthreads();

        // prefetch next slab while tensor pipe works
        if (kt + 1 < niter) {
            const int kg = (kt + 1) * 16;
            ra0 = ld_guard4(A + (size_t)(m0 + c0r) * K + kg + c0k, kg + c0k, K);
            ra1 = ld_guard4(A + (size_t)(m0 + c1r) * K + kg + c1k, kg + c1k, K);
            rw0 = ld_guard4(W + (size_t)(n0 + c0r) * K + kg + c0k, kg + c0k, K);
            rw1 = ld_guard4(W + (size_t)(n0 + c1r) * K + kg + c1k, kg + c1k, K);
        }

        uint32_t bh[4][2], bl[4][2];
#pragma unroll
        for (int j = 0; j < 4; j++) {
            int nc = wn + j * 8 + gid;
            bh[j][0] = Wh[buf][tig][nc];     bh[j][1] = Wh[buf][tig + 4][nc];
            bl[j][0] = Wl[buf][tig][nc];     bl[j][1] = Wl[buf][tig + 4][nc];
        }
#pragma unroll
        for (int mi = 0; mi < 4; mi++) {
            int mr = wm + mi * 16 + gid;
            uint32_t ah[4], al[4];
            ah[0] = Ah[buf][tig][mr];        ah[1] = Ah[buf][tig][mr + 8];
            ah[2] = Ah[buf][tig + 4][mr];    ah[3] = Ah[buf][tig + 4][mr + 8];
            al[0] = Al[buf][tig][mr];        al[1] = Al[buf][tig][mr + 8];
            al[2] = Al[buf][tig + 4][mr];    al[3] = Al[buf][tig + 4][mr + 8];
#pragma unroll
            for (int j = 0; j < 4; j++) {
                mma_bf16(acc[mi][j], ah, bh[j]);
                mma_bf16(acc[mi][j], al, bh[j]);
                mma_bf16(acc[mi][j], ah, bl[j]);
            }
        }
        // no trailing sync: next iter writes the other buffer, and the
        // STS(k+1)->sync(k+1) edge orders every warp's compute(k) before
        // any warp's STS(k+2) into this buffer.
    }

#pragma unroll
    for (int i = 0; i < 4; i++) {
#pragma unroll
        for (int j = 0; j < 4; j++) {
            int col = n0 + wn + j * 8 + tig * 2;
            float b0 = bias[col], b1 = bias[col + 1];
            int r0g = m0 + wm + i * 16 + gid;
            *(float2*)&C[(size_t)r0g * N + col] =
                make_float2(acc[i][j][0] + b0, acc[i][j][1] + b1);
            *(float2*)&C[(size_t)(r0g + 8) * N + col] =
                make_float2(acc[i][j][2] + b0, acc[i][j][3] + b1);
        }
    }
}

// ---------------- software grid barrier (volatile-load poll) ----------------
__device__ __forceinline__ void grid_sync(unsigned* bar, int ncta, unsigned* gen)
{
    __syncthreads();
    if (threadIdx.x == 0) {
        unsigned target = *gen + 1u;
        __threadfence();
        unsigned arr = atomicAdd(&bar[0], 1u);
        if (arr == (unsigned)(ncta - 1)) {
            atomicExch(&bar[0], 0u);
            __threadfence();
            atomicExch(&bar[1], target);
        } else {
            while (*(volatile unsigned*)&bar[1] < target) { }
        }
        __threadfence();
        *gen = target;
    }
    __syncthreads();
}

// ---------------- persistent weight-stationary GRU, tensor-core phase1 ------
template<int H, int G3, int T, int NCT, int KS>
__global__ __launch_bounds__(256, 2) void gru_persistent(
    const float* __restrict__ xp, const float* __restrict__ w_hh,
    const float* __restrict__ b_hh, float* __restrict__ hbuf,
    float* __restrict__ part, float* __restrict__ out,
    const int* __restrict__ perm, const int* __restrict__ lenp,
    unsigned* __restrict__ bar)
{
    constexpr int KC = 64;
    constexpr int NCTA = 2 * NCT * KS;
    extern __shared__ float sm[];
    uint32_t* Wh = (uint32_t*)sm;             // [KC][98]
    uint32_t* Wl = Wh + KC * 98;              // [KC][98]
    float*    Hs = (float*)(Wl + KC * 98);    // [KC][132]

    const int cta = blockIdx.x;
    const int d   = cta / (NCT * KS);
    const int ct  = (cta % (NCT * KS)) / KS;
    const int ks  = cta % KS;
    const int c0  = ct * 96;
    const int k0  = ks * KC;
    const int tid = threadIdx.x;
    const int wid = tid / 32, lane = tid % 32;
    const int gid = lane >> 2, tig = lane & 3;
    const int wm  = (wid >> 1) * 32;
    const int wn  = (wid & 1) * 48;

    for (int e = tid; e < KC * 96; e += 256) {
        int k = e % KC, c = e / KC;
        float w = w_hh[((size_t)d * G3 + c0 + c) * H + k0 + k];
        uint32_t wh = tf32_rna(w);
        Wh[k * 98 + c] = wh;
        Wl[k * 98 + c] = tf32_rna(w - __uint_as_float(wh));
    }

    const int myLen = lenp[wm];
    unsigned gen = 0;
    float* hcur = hbuf;
    float* hnxt = hbuf + 2 * B * H;
    const int total = 2 * B * H;
    const int nth   = NCTA * 256;

    for (int t = 0; t < T; t++) {
        const int te1 = (d == 0) ? t : (T - 1 - t);

        for (int e = tid; e < KC * B; e += 256) {
            int k = e % KC, r = e / KC;
            Hs[k * 132 + r] = hcur[((size_t)d * B + r) * H + k0 + k];
        }
        __syncthreads();

        if (te1 < myLen) {
            float acc[2][6][4];
#pragma unroll
            for (int i = 0; i < 2; i++)
#pragma unroll
                for (int j = 0; j < 6; j++)
#pragma unroll
                    for (int c = 0; c < 4; c++) acc[i][j][c] = 0.f;

#pragma unroll
            for (int k8 = 0; k8 < KC / 8; k8++) {
                const int kb = k8 * 8;
                uint32_t bh[6][2], bl[6][2];
#pragma unroll
                for (int j = 0; j < 6; j++) {
                    int c = wn + j * 8 + gid;
                    bh[j][0] = Wh[(kb + tig) * 98 + c];
                    bh[j][1] = Wh[(kb + tig + 4) * 98 + c];
                    bl[j][0] = Wl[(kb + tig) * 98 + c];
                    bl[j][1] = Wl[(kb + tig + 4) * 98 + c];
                }
#pragma unroll
                for (int mi = 0; mi < 2; mi++) {
                    int r = wm + mi * 16 + gid;
                    float h0 = Hs[(kb + tig) * 132 + r];
                    float h1 = Hs[(kb + tig) * 132 + r + 8];
                    float h2 = Hs[(kb + tig + 4) * 132 + r];
                    float h3 = Hs[(kb + tig + 4) * 132 + r + 8];
                    uint32_t ah[4], al[4];
                    ah[0] = tf32_rna(h0); al[0] = tf32_rna(h0 - __uint_as_float(ah[0]));
                    ah[1] = tf32_rna(h1); al[1] = tf32_rna(h1 - __uint_as_float(ah[1]));
                    ah[2] = tf32_rna(h2); al[2] = tf32_rna(h2 - __uint_as_float(ah[2]));
                    ah[3] = tf32_rna(h3); al[3] = tf32_rna(h3 - __uint_as_float(ah[3]));
#pragma unroll
                    for (int j = 0; j < 6; j++) {
                        mma_tf32(acc[mi][j], ah, bh[j]);
                        mma_tf32(acc[mi][j], al, bh[j]);
                        mma_tf32(acc[mi][j], ah, bl[j]);
                    }
                }
            }
#pragma unroll
            for (int mi = 0; mi < 2; mi++) {
                int r = wm + mi * 16 + gid;
#pragma unroll
                for (int j = 0; j < 6; j++) {
                    int col = c0 + wn + j * 8 + tig * 2;
                    float* p0 = part + (((size_t)ks * 2 + d) * B + r) * G3 + col;
                    float* p1 = part + (((size_t)ks * 2 + d) * B + r + 8) * G3 + col;
                    *(float2*)p0 = make_float2(acc[mi][j][0], acc[mi][j][1]);
                    *(float2*)p1 = make_float2(acc[mi][j][2], acc[mi][j][3]);
                }
            }
        }
        grid_sync(bar, NCTA, &gen);

        for (int it = cta * 256 + tid; it < total; it += nth) {
            int j  = it % H;
            int rr = (it / H) % B;
            int dd = it / (H * B);
            int te = (dd == 0) ? t : (T - 1 - t);
            int bo = perm[rr];
            int valid = te < lenp[rr];
            float hold = hcur[((size_t)dd * B + rr) * H + j];
            float hnew = hold;
            if (valid) {
                float hpr = 0.f, hpz = 0.f, hpn = 0.f;
#pragma unroll
                for (int s = 0; s < KS; s++) {
                    const float* pb = part + (((size_t)s * 2 + dd) * B + rr) * G3;
                    hpr += pb[j]; hpz += pb[H + j]; hpn += pb[2 * H + j];
                }
                const float* bb = b_hh + (size_t)dd * G3;
                hpr += bb[j]; hpz += bb[H + j]; hpn += bb[2 * H + j];
                const float* xr = xp + ((size_t)bo * T + te) * (2 * G3) + (size_t)dd * G3;
                float rg = 1.f / (1.f + expf(-(xr[j] + hpr)));
                float zg = 1.f / (1.f + expf(-(xr[H + j] + hpz)));
                float ng = tanhf(xr[2 * H + j] + rg * hpn);
                hnew = (1.f - zg) * ng + zg * hold;
            }
            hnxt[((size_t)dd * B + rr) * H + j] = hnew;
            out[((size_t)bo * T + te) * (2 * H) + dd * H + j] = valid ? hnew : 0.f;
        }
        grid_sync(bar, NCTA, &gen);
        float* tmp = hcur; hcur = hnxt; hnxt = tmp;
    }
}

// ---------------- segment means ----------------
__global__ __launch_bounds__(256) void seg_mean_kernel(
    const float* __restrict__ vf, const float* __restrict__ loc,
    const int* __restrict__ v_len,
    float* __restrict__ lmean, float* __restrict__ rmean, float* __restrict__ cat)
{
    const int b = blockIdx.x;
    const int col = blockIdx.y * 256 + threadIdx.x;
    const int vl = v_len[b];
    const float scale = (float)(vl - 1);
    const float l0 = loc[b * 2], l1 = loc[b * 2 + 1];
    const int cond = (l0 <= l1);
    const float lhi = cond ? l0 : 0.f;
    const float rlo = cond ? l1 : 1.f;
    const int lend   = (int)floorf(lhi * scale);
    const int rstart = (int)floorf(rlo * scale);
    const int rend   = vl - 1;
    const int ok_l = (0 <= lend);
    const int ok_r = (rstart <= rend);

    float ls = 0.f, rs = 0.f, gs = 0.f;
    for (int t = 0; t < TV; t++) {
        float v = vf[((size_t)b * TV + t) * 1024 + col];
        if (t < vl) gs += v;
        if (ok_l && t <= lend) ls += v;
        if (ok_r && t >= rstart && t <= rend) rs += v;
    }
    float lcnt = ok_l ? (float)(lend + 1) : 1.f;
    float rcnt = ok_r ? (float)(rend - rstart + 1) : 1.f;
    if (lcnt < 1.f) lcnt = 1.f;
    if (rcnt < 1.f) rcnt = 1.f;
    lmean[b * 1024 + col] = ls / lcnt;
    rmean[b * 1024 + col] = rs / rcnt;
    cat[(size_t)b * NCAT + 512 + col] = gs / (float)vl;
}

// ---------------- gather sen_fea ----------------
__global__ void gather_senfea(const float* __restrict__ words,
                              const int* __restrict__ lens,
                              float* __restrict__ out_sf, float* __restrict__ cat)
{
    const int b = blockIdx.x;
    const int t = lens[b] - 1;
    for (int c = threadIdx.x; c < 2 * SHID; c += blockDim.x) {
        float v = words[((size_t)b * TS + t) * (2 * SHID) + c];
        out_sf[(size_t)b * (2 * SHID) + c] = v;
        cat[(size_t)b * NCAT + c] = v;
    }
}

// ---------------- small GEMM with epilogue ----------------
__global__ __launch_bounds__(256) void gemm_small(
    const float* __restrict__ A, const float* __restrict__ W,
    const float* __restrict__ bias, const float* __restrict__ mul, int mulLd,
    float* __restrict__ C, int ldC, int M, int N, int K, int relu)
{
    const int n0 = blockIdx.x * 32, m0 = blockIdx.y * 32;
    __shared__ __align__(16) float As[32][34];
    __shared__ __align__(16) float Wsm[32][34];
    const int tid = threadIdx.x, ty = tid / 16, tx = tid % 16;
    float acc[2][2] = {{0.f, 0.f}, {0.f, 0.f}};

    for (int k0 = 0; k0 < K; k0 += 32) {
        for (int e = tid; e < 1024; e += 256) {
            int r = e / 32, k = e % 32;
            int kg = k0 + k;
            As[k][r]  = (kg < K) ? A[(size_t)(m0 + r) * K + kg] : 0.f;
            Wsm[k][r] = (kg < K) ? W[(size_t)(n0 + r) * K + kg] : 0.f;
        }
        __syncthreads();
#pragma unroll
        for (int k = 0; k < 32; k++) {
            float2 av = *(const float2*)&As[k][ty * 2];
            float2 wv = *(const float2*)&Wsm[k][tx * 2];
            acc[0][0] += av.x * wv.x;  acc[0][1] += av.x * wv.y;
            acc[1][0] += av.y * wv.x;  acc[1][1] += av.y * wv.y;
        }
        __syncthreads();
    }
#pragma unroll
    for (int i = 0; i < 2; i++) {
        int m = m0 + ty * 2 + i;
#pragma unroll
        for (int j = 0; j < 2; j++) {
            int n = n0 + tx * 2 + j;
            float v = acc[i][j] + bias[n];
            if (mul) v *= mul[(size_t)m * mulLd + n];
            if (relu) v = fmaxf(v, 0.f);
            C[(size_t)m * ldC + n] = v;
        }
    }
}

// ---------------- launch ----------------
extern "C" void kernel_launch(void* const* d_in, const int* in_sizes, int n_in,
                              void* d_out, int out_size)
{
    const float* gv     = (const float*)d_in[1];
    const float* sen    = (const float*)d_in[2];
    const float* loc    = (const float*)d_in[5];
    const int*   lens   = (const int*)  d_in[6];
    const int*   v_len  = (const int*)  d_in[7];
    const float* v_w_ih = (const float*)d_in[8];
    const float* v_w_hh = (const float*)d_in[9];
    const float* v_b_ih = (const float*)d_in[10];
    const float* v_b_hh = (const float*)d_in[11];
    const float* s_w_ih = (const float*)d_in[12];
    const float* s_w_hh = (const float*)d_in[13];
    const float* s_b_ih = (const float*)d_in[14];
    const float* s_b_hh = (const float*)d_in[15];
    const float* fc1_w  = (const float*)d_in[16];
    const float* fc1_b  = (const float*)d_in[17];
    const float* fc2_w  = (const float*)d_in[18];
    const float* fc2_b  = (const float*)d_in[19];
    const float* fc3_w  = (const float*)d_in[20];
    const float* fc3_b  = (const float*)d_in[21];
    const float* fc4_w  = (const float*)d_in[22];
    const float* fc4_b  = (const float*)d_in[23];

    float* out    = (float*)d_out;
    float* out_vf = out;
    float* out_sf = out + VF_ELEMS;
    float* out_ft = out + VF_ELEMS + SF_ELEMS;

    float *xp_v, *xp_s, *h_v, *h_s, *part_v, *part_s, *words;
    float *lmean, *rmean, *cat, *sproj;
    int *perm_v, *lenp_v, *perm_s, *lenp_s;
    unsigned* bar;
    cudaGetSymbolAddress((void**)&xp_v,   g_xp_v);
    cudaGetSymbolAddress((void**)&xp_s,   g_xp_s);
    cudaGetSymbolAddress((void**)&h_v,    g_h_v);
    cudaGetSymbolAddress((void**)&h_s,    g_h_s);
    cudaGetSymbolAddress((void**)&part_v, g_part_v);
    cudaGetSymbolAddress((void**)&part_s, g_part_s);
    cudaGetSymbolAddress((void**)&words,  g_words);
    cudaGetSymbolAddress((void**)&lmean,  g_lmean);
    cudaGetSymbolAddress((void**)&rmean,  g_rmean);
    cudaGetSymbolAddress((void**)&cat,    g_cat);
    cudaGetSymbolAddress((void**)&sproj,  g_sproj);
    cudaGetSymbolAddress((void**)&perm_v, g_perm_v);
    cudaGetSymbolAddress((void**)&lenp_v, g_lenp_v);
    cudaGetSymbolAddress((void**)&perm_s, g_perm_s);
    cudaGetSymbolAddress((void**)&lenp_s, g_lenp_s);
    cudaGetSymbolAddress((void**)&bar,    g_bar);

    const int SMEM = (2 * 64 * 98 + 64 * 132) * 4;
    cudaFuncSetAttribute(gru_persistent<512, 1536, 256, 16, 8>,
                         cudaFuncAttributeMaxDynamicSharedMemorySize, SMEM);
    cudaFuncSetAttribute(gru_persistent<256, 768, 40, 8, 4>,
                         cudaFuncAttributeMaxDynamicSharedMemorySize, SMEM);

    // 1. sort + zero
    sort_init_kernel<<<1, 128>>>(v_len, lens, perm_v, lenp_v, perm_s, lenp_s, bar);
    zero_h_kernel<<<(2*2*B*VHID + 255) / 256, 256>>>(h_v, h_s);

    // 2. input projections (3xBF16 tensor cores, staged hi/lo split)
    gemm_bf16x3<<<dim3(3072/128, (B*TV)/128), 256>>>(gv,  v_w_ih, v_b_ih, xp_v,
                                                     B*TV, 3072, VIN, v_len, TV);
    gemm_bf16x3<<<dim3(1536/128, (B*TS)/128), 256>>>(sen, s_w_ih, s_b_ih, xp_s,
                                                     B*TS, 1536, SIN, lens, TS);

    // 3. persistent visual GRU (256 CTAs, tensor-core phase1)
    gru_persistent<512, 1536, 256, 16, 8><<<256, 256, SMEM>>>(
        xp_v, v_w_hh, v_b_hh, h_v, part_v, out_vf, perm_v, lenp_v, bar);

    // 4. persistent sentence GRU (64 CTAs)
    gru_persistent<256, 768, 40, 8, 4><<<64, 256, SMEM>>>(
        xp_s, s_w_hh, s_b_hh, h_s, part_s, words, perm_s, lenp_s, bar + 2);

    // 5. sen_fea gather
    gather_senfea<<<B, 256>>>(words, lens, out_sf, cat);

    // 6. segment means + global mean
    seg_mean_kernel<<<dim3(B, 4), 256>>>(out_vf, loc, v_len, lmean, rmean, cat);

    // 7. FC stack
    gemm_small<<<dim3(LCROSS/32, B/32), 256>>>(out_sf, fc2_w, fc2_b, nullptr, 0,
                                               sproj, LCROSS, B, LCROSS, 2*SHID, 0);
    gemm_small<<<dim3(LCROSS/32, B/32), 256>>>(lmean, fc1_w, fc1_b, sproj, LCROSS,
                                               cat + 1536, NCAT, B, LCROSS, 2*VHID, 1);
    gemm_small<<<dim3(LCROSS/32, B/32), 256>>>(rmean, fc1_w, fc1_b, sproj, LCROSS,
                                               cat + 2048, NCAT, B, LCROSS, 2*VHID, 1);
    gemm_small<<<dim3(NLOC/32, B/32), 256>>>(loc, fc3_w, fc3_b, nullptr, 0,
                                             cat + 2560, NCAT, B, NLOC, 2, 1);
    gemm_small<<<dim3(NFEAT/32, B/32), 256>>>(cat, fc4_w, fc4_b, nullptr, 0,
                                              out_ft, NFEAT, B, NFEAT, NCAT, 1);
}

// round 8
// speedup vs baseline: 3.0619x; 1.2281x over previous
#include <cuda_runtime.h>
#include <cuda_bf16.h>
#include <math.h>
#include <stdint.h>

// ---------------- problem constants ----------------
#define B        128
#define TV       256
#define TS       40
#define VIN      1024
#define VHID     512
#define SIN      300
#define SHID     256
#define NCAT     2624
#define NFEAT    1024
#define LCROSS   512
#define NLOC     64

#define VF_ELEMS   ((size_t)B*TV*2*VHID)
#define SF_ELEMS   ((size_t)B*2*SHID)

// ---------------- scratch (__device__ globals) ----------------
__device__ float g_xp_v[(size_t)B*TV*3072];
__device__ float g_xp_s[(size_t)B*TS*1536];
__device__ float g_h_v[2*B*VHID];               // single buffer, in-place
__device__ float g_h_s[2*B*SHID];
__device__ float g_part_v[8*2*B*1536];
__device__ float g_part_s[4*2*B*768];
__device__ float g_words[(size_t)B*TS*2*SHID];
__device__ float g_lmean[B*1024];
__device__ float g_rmean[B*1024];
__device__ float g_cat[B*NCAT];
__device__ float g_sproj[B*LCROSS];
__device__ int   g_perm_v[B], g_lenp_v[B];
__device__ int   g_perm_s[B], g_lenp_s[B];
__device__ int   g_cnt_v[TV], g_cnt_s[TS];      // cnt[t] = #rows with len > t
__device__ unsigned g_bar[4];

// ---------------- init ----------------
__global__ void sort_init_kernel(const int* __restrict__ v_len,
                                 const int* __restrict__ lens,
                                 int* pv, int* lv, int* ps, int* ls,
                                 int* cv, int* cs, unsigned* bar)
{
    int i = threadIdx.x;
    if (i < 4) bar[i] = 0u;
    int a = v_len[i], rank = 0;
    for (int j = 0; j < B; j++) {
        int c = v_len[j];
        rank += (c > a) || (c == a && j < i);
    }
    pv[rank] = i; lv[rank] = a;
    a = lens[i]; rank = 0;
    for (int j = 0; j < B; j++) {
        int c = lens[j];
        rank += (c > a) || (c == a && j < i);
    }
    ps[rank] = i; ls[rank] = a;

    for (int t = i; t < TV; t += 128) {
        int c = 0;
        for (int j = 0; j < B; j++) c += (v_len[j] > t);
        cv[t] = c;
    }
    for (int t = i; t < TS; t += 128) {
        int c = 0;
        for (int j = 0; j < B; j++) c += (lens[j] > t);
        cs[t] = c;
    }
}

__global__ void zero_h_kernel(float* hv, float* hs) {
    int i = blockIdx.x * blockDim.x + threadIdx.x;
    if (i < 2*B*VHID) hv[i] = 0.f;
    if (i < 2*B*SHID) hs[i] = 0.f;
}

__global__ void zero_out_kernel(float4* p, int n4) {
    int i = blockIdx.x * blockDim.x + threadIdx.x;
    if (i < n4) p[i] = make_float4(0.f, 0.f, 0.f, 0.f);
}

// ---------------- numeric helpers ----------------
__device__ __forceinline__ uint32_t tf32_rna(float x) {
    uint32_t r;
    asm("cvt.rna.tf32.f32 %0, %1;" : "=r"(r) : "f"(x));
    return r;
}
__device__ __forceinline__ void mma_tf32(float* d, const uint32_t* a, const uint32_t* b) {
    asm volatile(
        "mma.sync.aligned.m16n8k8.row.col.f32.tf32.tf32.f32 "
        "{%0,%1,%2,%3}, {%4,%5,%6,%7}, {%8,%9}, {%0,%1,%2,%3};"
        : "+f"(d[0]), "+f"(d[1]), "+f"(d[2]), "+f"(d[3])
        : "r"(a[0]), "r"(a[1]), "r"(a[2]), "r"(a[3]), "r"(b[0]), "r"(b[1]));
}
__device__ __forceinline__ void mma_bf16(float* d, const uint32_t* a, const uint32_t* b) {
    asm volatile(
        "mma.sync.aligned.m16n8k16.row.col.f32.bf16.bf16.f32 "
        "{%0,%1,%2,%3}, {%4,%5,%6,%7}, {%8,%9}, {%0,%1,%2,%3};"
        : "+f"(d[0]), "+f"(d[1]), "+f"(d[2]), "+f"(d[3])
        : "r"(a[0]), "r"(a[1]), "r"(a[2]), "r"(a[3]), "r"(b[0]), "r"(b[1]));
}
__device__ __forceinline__ void ldsm_x4(uint32_t* r, uint32_t saddr) {
    asm volatile("ldmatrix.sync.aligned.m8n8.x4.shared.b16 {%0,%1,%2,%3}, [%4];"
                 : "=r"(r[0]), "=r"(r[1]), "=r"(r[2]), "=r"(r[3]) : "r"(saddr));
}
__device__ __forceinline__ uint32_t bfpack(__nv_bfloat16 lo, __nv_bfloat16 hi) {
    uint32_t l = __bfloat16_as_ushort(lo);
    uint32_t h = __bfloat16_as_ushort(hi);
    return l | (h << 16);
}
__device__ __forceinline__ void bfsplit2(float x0, float x1,
                                         uint32_t& hi, uint32_t& lo) {
    __nv_bfloat16 h0 = __float2bfloat16_rn(x0);
    __nv_bfloat16 h1 = __float2bfloat16_rn(x1);
    hi = bfpack(h0, h1);
    __nv_bfloat16 l0 = __float2bfloat16_rn(x0 - __bfloat162float(h0));
    __nv_bfloat16 l1 = __float2bfloat16_rn(x1 - __bfloat162float(h1));
    lo = bfpack(l0, l1);
}
__device__ __forceinline__ float4 ld_guard4(const float* p, int kg, int K) {
    if (kg + 4 <= K) return *(const float4*)p;
    float4 v;
    v.x = (kg     < K) ? p[0] : 0.f;
    v.y = (kg + 1 < K) ? p[1] : 0.f;
    v.z = (kg + 2 < K) ? p[2] : 0.f;
    v.w = (kg + 3 < K) ? p[3] : 0.f;
    return v;
}
__device__ __forceinline__ float fast_sigmoid(float x) {
    return __fdividef(1.f, 1.f + __expf(-x));
}
__device__ __forceinline__ float fast_tanh(float x) {
    return __fdividef(2.f, 1.f + __expf(-2.f * x)) - 1.f;
}

// ---------------- 3xBF16 tensor-core GEMM with ldmatrix fragments ----------
// smem layout: [2 buf][128 rows][12 u32] per operand half (8 used = 16 bf16,
// stride 12 keeps ldmatrix phases conflict-free). 12 LDSM.x4 per warp/iter.
#define GEMM_SMEM (4 * 2 * 128 * 12 * 4)     // 49152 B
__global__ __launch_bounds__(256, 2) void gemm_bf16x3(
    const float* __restrict__ A, const float* __restrict__ W,
    const float* __restrict__ bias, float* __restrict__ C,
    int M, int N, int K, const int* __restrict__ lens, int T)
{
    extern __shared__ uint32_t dsm[];
    const int AH = 0, AL = 2*128*12, WH = 2*AL, WL = 3*AL;  // u32 offsets
    __shared__ int s_any;

    const int n0 = blockIdx.x * 128;
    const int m0 = blockIdx.y * 128;
    const int tid = threadIdx.x;

    if (lens) {
        if (tid == 0) {
            int any = 0;
            for (int r = 0; r < 128; r++) {
                int row = m0 + r;
                if (row % T < lens[row / T]) { any = 1; break; }
            }
            s_any = any;
        }
        __syncthreads();
        if (!s_any) return;
    }

    const int wid  = tid / 32, lane = tid % 32;
    const int wm   = (wid / 4) * 64;
    const int wn   = (wid % 4) * 32;
    const int gid  = lane >> 2, tig = lane & 3;
    const int quad = lane >> 3, lrow = lane & 7;
    // ldmatrix per-lane address pieces
    const int arow = ((quad & 1) << 3) + lrow;   // A: r0/r1 = m0-7/m8-15 k0-7; r2/r3 = k8-15
    const int ak2  = (quad >> 1) * 4;
    const int wrow = ((quad >> 1) << 3) + lrow;  // W: r0/r1 = n0-7 k0-7/k8-15; r2/r3 = n8-15
    const int wk2  = (quad & 1) * 4;
    const uint32_t sbase = (uint32_t)__cvta_generic_to_shared(dsm);
    const int niter = (K + 15) >> 4;

    const int c0r = tid >> 2,          c0k = (tid & 3) * 4;
    const int c1r = (tid + 256) >> 2,  c1k = ((tid + 256) & 3) * 4;

    float acc[4][4][4];
#pragma unroll
    for (int i = 0; i < 4; i++)
#pragma unroll
        for (int j = 0; j < 4; j++)
#pragma unroll
            for (int c = 0; c < 4; c++) acc[i][j][c] = 0.f;

    float4 ra0, ra1, rw0, rw1;
    ra0 = ld_guard4(A + (size_t)(m0 + c0r) * K + c0k, c0k, K);
    ra1 = ld_guard4(A + (size_t)(m0 + c1r) * K + c1k, c1k, K);
    rw0 = ld_guard4(W + (size_t)(n0 + c0r) * K + c0k, c0k, K);
    rw1 = ld_guard4(W + (size_t)(n0 + c1r) * K + c1k, c1k, K);

    for (int kt = 0; kt < niter; kt++) {
        const int buf = kt & 1;
        const int bo = buf * 128;
        {
            uint32_t h, l;
            int k2 = c0k >> 1;
            int r0i = (bo + c0r) * 12, r1i = (bo + c1r) * 12;
            bfsplit2(ra0.x, ra0.y, h, l); dsm[AH + r0i + k2] = h;     dsm[AL + r0i + k2] = l;
            bfsplit2(ra0.z, ra0.w, h, l); dsm[AH + r0i + k2 + 1] = h; dsm[AL + r0i + k2 + 1] = l;
            bfsplit2(rw0.x, rw0.y, h, l); dsm[WH + r0i + k2] = h;     dsm[WL + r0i + k2] = l;
            bfsplit2(rw0.z, rw0.w, h, l); dsm[WH + r0i + k2 + 1] = h; dsm[WL + r0i + k2 + 1] = l;
            k2 = c1k >> 1;
            bfsplit2(ra1.x, ra1.y, h, l); dsm[AH + r1i + k2] = h;     dsm[AL + r1i + k2] = l;
            bfsplit2(ra1.z, ra1.w, h, l); dsm[AH + r1i + k2 + 1] = h; dsm[AL + r1i + k2 + 1] = l;
            bfsplit2(rw1.x, rw1.y, h, l); dsm[WH + r1i + k2] = h;     dsm[WL + r1i + k2] = l;
            bfsplit2(rw1.z, rw1.w, h, l); dsm[WH + r1i + k2 + 1] = h; dsm[WL + r1i + k2 + 1] = l;
        }
        __syncthreads();

        if (kt + 1 < niter) {
            const int kg = (kt + 1) * 16;
            ra0 = ld_guard4(A + (size_t)(m0 + c0r) * K + kg + c0k, kg + c0k, K);
            ra1 = ld_guard4(A + (size_t)(m0 + c1r) * K + kg + c1k, kg + c1k, K);
            rw0 = ld_guard4(W + (size_t)(n0 + c0r) * K + kg + c0k, kg + c0k, K);
            rw1 = ld_guard4(W + (size_t)(n0 + c1r) * K + kg + c1k, kg + c1k, K);
        }

        uint32_t bh[4][2], bl[4][2];
#pragma unroll
        for (int jp = 0; jp < 2; jp++) {
            uint32_t r[4];
            uint32_t a = sbase + (WH + (bo + wn + jp * 16 + wrow) * 12 + wk2) * 4;
            ldsm_x4(r, a);
            bh[jp*2][0] = r[0]; bh[jp*2][1] = r[1];
            bh[jp*2+1][0] = r[2]; bh[jp*2+1][1] = r[3];
            ldsm_x4(r, a + (WL - WH) * 4);
            bl[jp*2][0] = r[0]; bl[jp*2][1] = r[1];
            bl[jp*2+1][0] = r[2]; bl[jp*2+1][1] = r[3];
        }
#pragma unroll
        for (int mi = 0; mi < 4; mi++) {
            uint32_t ah[4], al[4];
            uint32_t a = sbase + (AH + (bo + wm + mi * 16 + arow) * 12 + ak2) * 4;
            ldsm_x4(ah, a);
            ldsm_x4(al, a + (AL - AH) * 4);
#pragma unroll
            for (int j = 0; j < 4; j++) {
                mma_bf16(acc[mi][j], ah, bh[j]);
                mma_bf16(acc[mi][j], al, bh[j]);
                mma_bf16(acc[mi][j], ah, bl[j]);
            }
        }
    }

#pragma unroll
    for (int i = 0; i < 4; i++) {
#pragma unroll
        for (int j = 0; j < 4; j++) {
            int col = n0 + wn + j * 8 + tig * 2;
            float b0 = bias[col], b1 = bias[col + 1];
            int r0g = m0 + wm + i * 16 + gid;
            *(float2*)&C[(size_t)r0g * N + col] =
                make_float2(acc[i][j][0] + b0, acc[i][j][1] + b1);
            *(float2*)&C[(size_t)(r0g + 8) * N + col] =
                make_float2(acc[i][j][2] + b0, acc[i][j][3] + b1);
        }
    }
}

// ---------------- software grid barrier ----------------
__device__ __forceinline__ void grid_sync(unsigned* bar, int ncta, unsigned* gen)
{
    __syncthreads();
    if (threadIdx.x == 0) {
        unsigned target = *gen + 1u;
        __threadfence();
        unsigned arr = atomicAdd(&bar[0], 1u);
        if (arr == (unsigned)(ncta - 1)) {
            atomicExch(&bar[0], 0u);
            __threadfence();
            atomicExch(&bar[1], target);
        } else {
            while (*(volatile unsigned*)&bar[1] < target) { }
        }
        __threadfence();
        *gen = target;
    }
    __syncthreads();
}

// ---------------- persistent GRU: tensor phase1, valid-only phase2 ---------
// h updated IN PLACE (barriers order phase1 reads vs phase2 writes).
// out_vf pre-zeroed; phase2 touches only valid (dir,row) prefix per step.
template<int H, int G3, int T, int NCT, int KS>
__global__ __launch_bounds__(256, 2) void gru_persistent(
    const float* __restrict__ xp, const float* __restrict__ w_hh,
    const float* __restrict__ b_hh, float* __restrict__ hbuf,
    float* __restrict__ part, float* __restrict__ out,
    const int* __restrict__ perm, const int* __restrict__ cnt,
    unsigned* __restrict__ bar)
{
    constexpr int KC = 64;
    constexpr int NCTA = 2 * NCT * KS;
    extern __shared__ float sm[];
    uint32_t* Wh = (uint32_t*)sm;             // [KC][98]
    uint32_t* Wl = Wh + KC * 98;
    float*    Hs = (float*)(Wl + KC * 98);    // [KC][132]

    const int cta = blockIdx.x;
    const int d   = cta / (NCT * KS);
    const int ct  = (cta % (NCT * KS)) / KS;
    const int ks  = cta % KS;
    const int c0  = ct * 96;
    const int k0  = ks * KC;
    const int tid = threadIdx.x;
    const int wid = tid / 32, lane = tid % 32;
    const int gid = lane >> 2, tig = lane & 3;
    const int wm  = (wid >> 1) * 32;
    const int wn  = (wid & 1) * 48;

    for (int e = tid; e < KC * 96; e += 256) {
        int k = e % KC, c = e / KC;
        float w = w_hh[((size_t)d * G3 + c0 + c) * H + k0 + k];
        uint32_t wh = tf32_rna(w);
        Wh[k * 98 + c] = wh;
        Wl[k * 98 + c] = tf32_rna(w - __uint_as_float(wh));
    }

    unsigned gen = 0;
    const int nth = NCTA * 256;

    for (int t = 0; t < T; t++) {
        const int cnt0 = cnt[t];
        const int cnt1 = cnt[T - 1 - t];
        const int cd   = (d == 0) ? cnt0 : cnt1;
        const int rc   = (cd + 31) & ~31;      // staged row prefix

        for (int e = tid; e < KC * rc; e += 256) {
            int k = e % KC, r = e / KC;
            Hs[k * 132 + r] = hbuf[((size_t)d * B + r) * H + k0 + k];
        }
        __syncthreads();

        if (wm < cd) {
            float acc[2][6][4];
#pragma unroll
            for (int i = 0; i < 2; i++)
#pragma unroll
                for (int j = 0; j < 6; j++)
#pragma unroll
                    for (int c = 0; c < 4; c++) acc[i][j][c] = 0.f;

#pragma unroll
            for (int k8 = 0; k8 < KC / 8; k8++) {
                const int kb = k8 * 8;
                uint32_t bh[6][2], bl[6][2];
#pragma unroll
                for (int j = 0; j < 6; j++) {
                    int c = wn + j * 8 + gid;
                    bh[j][0] = Wh[(kb + tig) * 98 + c];
                    bh[j][1] = Wh[(kb + tig + 4) * 98 + c];
                    bl[j][0] = Wl[(kb + tig) * 98 + c];
                    bl[j][1] = Wl[(kb + tig + 4) * 98 + c];
                }
#pragma unroll
                for (int mi = 0; mi < 2; mi++) {
                    int r = wm + mi * 16 + gid;
                    float h0 = Hs[(kb + tig) * 132 + r];
                    float h1 = Hs[(kb + tig) * 132 + r + 8];
                    float h2 = Hs[(kb + tig + 4) * 132 + r];
                    float h3 = Hs[(kb + tig + 4) * 132 + r + 8];
                    uint32_t ah[4], al[4];
                    ah[0] = tf32_rna(h0); al[0] = tf32_rna(h0 - __uint_as_float(ah[0]));
                    ah[1] = tf32_rna(h1); al[1] = tf32_rna(h1 - __uint_as_float(ah[1]));
                    ah[2] = tf32_rna(h2); al[2] = tf32_rna(h2 - __uint_as_float(ah[2]));
                    ah[3] = tf32_rna(h3); al[3] = tf32_rna(h3 - __uint_as_float(ah[3]));
#pragma unroll
                    for (int j = 0; j < 6; j++) {
                        mma_tf32(acc[mi][j], ah, bh[j]);
                        mma_tf32(acc[mi][j], al, bh[j]);
                        mma_tf32(acc[mi][j], ah, bl[j]);
                    }
                }
            }
#pragma unroll
            for (int mi = 0; mi < 2; mi++) {
                int r = wm + mi * 16 + gid;
#pragma unroll
                for (int j = 0; j < 6; j++) {
                    int col = c0 + wn + j * 8 + tig * 2;
                    float* p0 = part + (((size_t)ks * 2 + d) * B + r) * G3 + col;
                    float* p1 = part + (((size_t)ks * 2 + d) * B + r + 8) * G3 + col;
                    *(float2*)p0 = make_float2(acc[mi][j][0], acc[mi][j][1]);
                    *(float2*)p1 = make_float2(acc[mi][j][2], acc[mi][j][3]);
                }
            }
        }
        grid_sync(bar, NCTA, &gen);

        // phase2: valid elements only (rows sorted desc by length)
        const int n0e = cnt0 * H;
        const int total = n0e + cnt1 * H;
        for (int it = cta * 256 + tid; it < total; it += nth) {
            int dd = (it >= n0e);
            int loc = dd ? (it - n0e) : it;
            int rr = loc / H, j = loc % H;
            int te = dd ? (T - 1 - t) : t;
            int bo = perm[rr];
            float hold = hbuf[((size_t)dd * B + rr) * H + j];
            float hpr = 0.f, hpz = 0.f, hpn = 0.f;
#pragma unroll
            for (int s = 0; s < KS; s++) {
                const float* pb = part + (((size_t)s * 2 + dd) * B + rr) * G3;
                hpr += pb[j]; hpz += pb[H + j]; hpn += pb[2 * H + j];
            }
            const float* bb = b_hh + (size_t)dd * G3;
            hpr += bb[j]; hpz += bb[H + j]; hpn += bb[2 * H + j];
            const float* xr = xp + ((size_t)bo * T + te) * (2 * G3) + (size_t)dd * G3;
            float rg = fast_sigmoid(xr[j] + hpr);
            float zg = fast_sigmoid(xr[H + j] + hpz);
            float ng = fast_tanh(xr[2 * H + j] + rg * hpn);
            float hnew = (1.f - zg) * ng + zg * hold;
            hbuf[((size_t)dd * B + rr) * H + j] = hnew;
            out[((size_t)bo * T + te) * (2 * H) + dd * H + j] = hnew;
        }
        grid_sync(bar, NCTA, &gen);
    }
}

// ---------------- segment means ----------------
__global__ __launch_bounds__(256) void seg_mean_kernel(
    const float* __restrict__ vf, const float* __restrict__ loc,
    const int* __restrict__ v_len,
    float* __restrict__ lmean, float* __restrict__ rmean, float* __restrict__ cat)
{
    const int b = blockIdx.x;
    const int col = blockIdx.y * 256 + threadIdx.x;
    const int vl = v_len[b];
    const float scale = (float)(vl - 1);
    const float l0 = loc[b * 2], l1 = loc[b * 2 + 1];
    const int cond = (l0 <= l1);
    const float lhi = cond ? l0 : 0.f;
    const float rlo = cond ? l1 : 1.f;
    const int lend   = (int)floorf(lhi * scale);
    const int rstart = (int)floorf(rlo * scale);
    const int rend   = vl - 1;
    const int ok_l = (0 <= lend);
    const int ok_r = (rstart <= rend);

    float ls = 0.f, rs = 0.f, gs = 0.f;
    for (int t = 0; t < TV; t++) {
        float v = vf[((size_t)b * TV + t) * 1024 + col];
        if (t < vl) gs += v;
        if (ok_l && t <= lend) ls += v;
        if (ok_r && t >= rstart && t <= rend) rs += v;
    }
    float lcnt = ok_l ? (float)(lend + 1) : 1.f;
    float rcnt = ok_r ? (float)(rend - rstart + 1) : 1.f;
    if (lcnt < 1.f) lcnt = 1.f;
    if (rcnt < 1.f) rcnt = 1.f;
    lmean[b * 1024 + col] = ls / lcnt;
    rmean[b * 1024 + col] = rs / rcnt;
    cat[(size_t)b * NCAT + 512 + col] = gs / (float)vl;
}

// ---------------- gather sen_fea ----------------
__global__ void gather_senfea(const float* __restrict__ words,
                              const int* __restrict__ lens,
                              float* __restrict__ out_sf, float* __restrict__ cat)
{
    const int b = blockIdx.x;
    const int t = lens[b] - 1;
    for (int c = threadIdx.x; c < 2 * SHID; c += blockDim.x) {
        float v = words[((size_t)b * TS + t) * (2 * SHID) + c];
        out_sf[(size_t)b * (2 * SHID) + c] = v;
        cat[(size_t)b * NCAT + c] = v;
    }
}

// ---------------- small GEMM with epilogue ----------------
__global__ __launch_bounds__(256) void gemm_small(
    const float* __restrict__ A, const float* __restrict__ W,
    const float* __restrict__ bias, const float* __restrict__ mul, int mulLd,
    float* __restrict__ C, int ldC, int M, int N, int K, int relu)
{
    const int n0 = blockIdx.x * 32, m0 = blockIdx.y * 32;
    __shared__ __align__(16) float As[32][34];
    __shared__ __align__(16) float Wsm[32][34];
    const int tid = threadIdx.x, ty = tid / 16, tx = tid % 16;
    float acc[2][2] = {{0.f, 0.f}, {0.f, 0.f}};

    for (int k0 = 0; k0 < K; k0 += 32) {
        for (int e = tid; e < 1024; e += 256) {
            int r = e / 32, k = e % 32;
            int kg = k0 + k;
            As[k][r]  = (kg < K) ? A[(size_t)(m0 + r) * K + kg] : 0.f;
            Wsm[k][r] = (kg < K) ? W[(size_t)(n0 + r) * K + kg] : 0.f;
        }
        __syncthreads();
#pragma unroll
        for (int k = 0; k < 32; k++) {
            float2 av = *(const float2*)&As[k][ty * 2];
            float2 wv = *(const float2*)&Wsm[k][tx * 2];
            acc[0][0] += av.x * wv.x;  acc[0][1] += av.x * wv.y;
            acc[1][0] += av.y * wv.x;  acc[1][1] += av.y * wv.y;
        }
        __syncthreads();
    }
#pragma unroll
    for (int i = 0; i < 2; i++) {
        int m = m0 + ty * 2 + i;
#pragma unroll
        for (int j = 0; j < 2; j++) {
            int n = n0 + tx * 2 + j;
            float v = acc[i][j] + bias[n];
            if (mul) v *= mul[(size_t)m * mulLd + n];
            if (relu) v = fmaxf(v, 0.f);
            C[(size_t)m * ldC + n] = v;
        }
    }
}

// ---------------- launch ----------------
extern "C" void kernel_launch(void* const* d_in, const int* in_sizes, int n_in,
                              void* d_out, int out_size)
{
    const float* gv     = (const float*)d_in[1];
    const float* sen    = (const float*)d_in[2];
    const float* loc    = (const float*)d_in[5];
    const int*   lens   = (const int*)  d_in[6];
    const int*   v_len  = (const int*)  d_in[7];
    const float* v_w_ih = (const float*)d_in[8];
    const float* v_w_hh = (const float*)d_in[9];
    const float* v_b_ih = (const float*)d_in[10];
    const float* v_b_hh = (const float*)d_in[11];
    const float* s_w_ih = (const float*)d_in[12];
    const float* s_w_hh = (const float*)d_in[13];
    const float* s_b_ih = (const float*)d_in[14];
    const float* s_b_hh = (const float*)d_in[15];
    const float* fc1_w  = (const float*)d_in[16];
    const float* fc1_b  = (const float*)d_in[17];
    const float* fc2_w  = (const float*)d_in[18];
    const float* fc2_b  = (const float*)d_in[19];
    const float* fc3_w  = (const float*)d_in[20];
    const float* fc3_b  = (const float*)d_in[21];
    const float* fc4_w  = (const float*)d_in[22];
    const float* fc4_b  = (const float*)d_in[23];

    float* out    = (float*)d_out;
    float* out_vf = out;
    float* out_sf = out + VF_ELEMS;
    float* out_ft = out + VF_ELEMS + SF_ELEMS;

    float *xp_v, *xp_s, *h_v, *h_s, *part_v, *part_s, *words;
    float *lmean, *rmean, *cat, *sproj;
    int *perm_v, *lenp_v, *perm_s, *lenp_s, *cnt_v, *cnt_s;
    unsigned* bar;
    cudaGetSymbolAddress((void**)&xp_v,   g_xp_v);
    cudaGetSymbolAddress((void**)&xp_s,   g_xp_s);
    cudaGetSymbolAddress((void**)&h_v,    g_h_v);
    cudaGetSymbolAddress((void**)&h_s,    g_h_s);
    cudaGetSymbolAddress((void**)&part_v, g_part_v);
    cudaGetSymbolAddress((void**)&part_s, g_part_s);
    cudaGetSymbolAddress((void**)&words,  g_words);
    cudaGetSymbolAddress((void**)&lmean,  g_lmean);
    cudaGetSymbolAddress((void**)&rmean,  g_rmean);
    cudaGetSymbolAddress((void**)&cat,    g_cat);
    cudaGetSymbolAddress((void**)&sproj,  g_sproj);
    cudaGetSymbolAddress((void**)&perm_v, g_perm_v);
    cudaGetSymbolAddress((void**)&lenp_v, g_lenp_v);
    cudaGetSymbolAddress((void**)&perm_s, g_perm_s);
    cudaGetSymbolAddress((void**)&lenp_s, g_lenp_s);
    cudaGetSymbolAddress((void**)&cnt_v,  g_cnt_v);
    cudaGetSymbolAddress((void**)&cnt_s,  g_cnt_s);
    cudaGetSymbolAddress((void**)&bar,    g_bar);

    const int GRU_SMEM = (2 * 64 * 98 + 64 * 132) * 4;
    cudaFuncSetAttribute(gru_persistent<512, 1536, 256, 16, 8>,
                         cudaFuncAttributeMaxDynamicSharedMemorySize, GRU_SMEM);
    cudaFuncSetAttribute(gru_persistent<256, 768, 40, 8, 4>,
                         cudaFuncAttributeMaxDynamicSharedMemorySize, GRU_SMEM);
    cudaFuncSetAttribute(gemm_bf16x3,
                         cudaFuncAttributeMaxDynamicSharedMemorySize, GEMM_SMEM);

    // 1. sort + counts + zero h + zero visual output region
    sort_init_kernel<<<1, 128>>>(v_len, lens, perm_v, lenp_v, perm_s, lenp_s,
                                 cnt_v, cnt_s, bar);
    zero_h_kernel<<<(2*B*VHID + 255) / 256, 256>>>(h_v, h_s);
    zero_out_kernel<<<(int)(VF_ELEMS/4 + 255) / 256, 256>>>((float4*)out_vf,
                                                            (int)(VF_ELEMS/4));

    // 2. input projections (3xBF16, ldmatrix fragments)
    gemm_bf16x3<<<dim3(3072/128, (B*TV)/128), 256, GEMM_SMEM>>>(
        gv,  v_w_ih, v_b_ih, xp_v, B*TV, 3072, VIN, v_len, TV);
    gemm_bf16x3<<<dim3(1536/128, (B*TS)/128), 256, GEMM_SMEM>>>(
        sen, s_w_ih, s_b_ih, xp_s, B*TS, 1536, SIN, lens, TS);

    // 3. persistent visual GRU
    gru_persistent<512, 1536, 256, 16, 8><<<256, 256, GRU_SMEM>>>(
        xp_v, v_w_hh, v_b_hh, h_v, part_v, out_vf, perm_v, cnt_v, bar);

    // 4. persistent sentence GRU
    gru_persistent<256, 768, 40, 8, 4><<<64, 256, GRU_SMEM>>>(
        xp_s, s_w_hh, s_b_hh, h_s, part_s, words, perm_s, cnt_s, bar + 2);

    // 5. sen_fea gather
    gather_senfea<<<B, 256>>>(words, lens, out_sf, cat);

    // 6. segment means + global mean
    seg_mean_kernel<<<dim3(B, 4), 256>>>(out_vf, loc, v_len, lmean, rmean, cat);

    // 7. FC stack
    gemm_small<<<dim3(LCROSS/32, B/32), 256>>>(out_sf, fc2_w, fc2_b, nullptr, 0,
                                               sproj, LCROSS, B, LCROSS, 2*SHID, 0);
    gemm_small<<<dim3(LCROSS/32, B/32), 256>>>(lmean, fc1_w, fc1_b, sproj, LCROSS,
                                               cat + 1536, NCAT, B, LCROSS, 2*VHID, 1);
    gemm_small<<<dim3(LCROSS/32, B/32), 256>>>(rmean, fc1_w, fc1_b, sproj, LCROSS,
                                               cat + 2048, NCAT, B, LCROSS, 2*VHID, 1);
    gemm_small<<<dim3(NLOC/32, B/32), 256>>>(loc, fc3_w, fc3_b, nullptr, 0,
                                             cat + 2560, NCAT, B, NLOC, 2, 1);
    gemm_small<<<dim3(NFEAT/32, B/32), 256>>>(cat, fc4_w, fc4_b, nullptr, 0,
                                              out_ft, NFEAT, B, NFEAT, NCAT, 1);
}